// round 14
// baseline (speedup 1.0000x reference)
#include <cuda_runtime.h>
#include <cuda_bf16.h>
#include <math.h>
#include <stdint.h>

#define BB 8
#define LL 1024
#define DM 512
#define HH 8
#define HD 64
#define DFF 2048
#define BLN (BB*LL)
#define MAXK 50
#define QKVN 1536

// ---------------- scratch (device globals; no allocations allowed) ----------
__device__ __align__(16) unsigned g_qkvbf[(size_t)BLN*768];
__device__ __align__(16) unsigned g_pbf[(size_t)64*1024*512];
__device__ __align__(16) unsigned g_vp[(size_t)8*512*512];
__device__ __align__(16) unsigned g_t0b[BLN*256];
__device__ __align__(16) unsigned g_x2b[BLN*256];
__device__ __align__(16) unsigned g_ggb[BLN*256];
__device__ __align__(16) unsigned g_hidb[(size_t)BLN*1024];
__device__ __align__(16) unsigned g_xb[BLN*256];
__device__ __align__(16) unsigned g_wqkvT[QKVN*256];   // [1536][512] bf16 (W^T)
__device__ __align__(16) unsigned g_wopT[512*256];     // [512][512]  bf16 (Wo^T)
__device__ __align__(16) unsigned g_wgb[512*256];      // [512][512]  bf16
__device__ __align__(16) unsigned g_w1b[2048*256];     // [2048][512] bf16
__device__ __align__(16) unsigned g_w2b[512*1024];     // [512][2048] bf16
__device__ float g_bqkv[QKVN];
__device__ float g_x1[BLN*DM];
__device__ float g_x2[BLN*DM];
__device__ float g_xg[BB*8*DM];
__device__ float g_w [BB*MAXK];
__device__ int   g_kk[BB];

// ---------------- helpers ----------------------------------------------------
__device__ __forceinline__ unsigned pack2bf(float a, float b) {
    __nv_bfloat162 w;
    w.x = __float2bfloat16_rn(a);
    w.y = __float2bfloat16_rn(b);
    return *(unsigned*)&w;
}

__device__ __forceinline__ void mma_bf16(float c[4], const unsigned a[4], const unsigned b[2]) {
    asm volatile(
        "mma.sync.aligned.m16n8k16.row.col.f32.bf16.bf16.f32 "
        "{%0,%1,%2,%3},{%4,%5,%6,%7},{%8,%9},{%0,%1,%2,%3};"
        : "+f"(c[0]), "+f"(c[1]), "+f"(c[2]), "+f"(c[3])
        : "r"(a[0]), "r"(a[1]), "r"(a[2]), "r"(a[3]), "r"(b[0]), "r"(b[1]));
}

__device__ __forceinline__ void ldsm_x4(unsigned r[4], uint32_t addr) {
    asm volatile("ldmatrix.sync.aligned.m8n8.x4.shared.b16 {%0,%1,%2,%3}, [%4];"
        : "=r"(r[0]), "=r"(r[1]), "=r"(r[2]), "=r"(r[3]) : "r"(addr));
}
__device__ __forceinline__ void ldsm_x2(unsigned r[2], uint32_t addr) {
    asm volatile("ldmatrix.sync.aligned.m8n8.x2.shared.b16 {%0,%1}, [%2];"
        : "=r"(r[0]), "=r"(r[1]) : "r"(addr));
}

__device__ __forceinline__ void cpa16(void* dst, const void* src) {
    unsigned d = (unsigned)__cvta_generic_to_shared(dst);
    asm volatile("cp.async.cg.shared.global [%0], [%1], 16;" :: "r"(d), "l"(src));
}
__device__ __forceinline__ void cpa_commit() { asm volatile("cp.async.commit_group;"); }
template<int N>
__device__ __forceinline__ void cpa_wait() { asm volatile("cp.async.wait_group %0;" :: "n"(N)); }
__device__ __forceinline__ uint32_t s2u(const void* p) {
    return (uint32_t)__cvta_generic_to_shared(p);
}

// ---------------- merged pack kernel -------------------------------------------
__device__ __forceinline__ void tpose_blk(const float* __restrict__ W,
                                          __nv_bfloat16* __restrict__ out,
                                          int rowOff, int idx)
{
    __shared__ float t[32][33];
    int k0 = (idx & 15) * 32, n0 = (idx >> 4) * 32;
    int tx = threadIdx.x & 31, ty = threadIdx.x >> 5;
#pragma unroll
    for (int i = 0; i < 4; i++)
        t[ty + 8 * i][tx] = W[(size_t)(k0 + ty + 8 * i) * 512 + n0 + tx];
    __syncthreads();
#pragma unroll
    for (int i = 0; i < 4; i++)
        out[(size_t)(rowOff + n0 + ty + 8 * i) * 512 + k0 + tx] =
            __float2bfloat16_rn(t[tx][ty + 8 * i]);
}
__device__ __forceinline__ void cvt_blk(const float4* __restrict__ src,
                                        uint2* __restrict__ dst, int idx, int n4)
{
    int i = idx * 256 + threadIdx.x;
    if (i < n4) {
        float4 v = src[i];
        uint2 u = { pack2bf(v.x, v.y), pack2bf(v.z, v.w) };
        dst[i] = u;
    }
}

// blocks: [0,256) tpQ | [256,512) tpK | [512,768) tpV | [768,1024) tpO
//   [1024,1280) gate | [1280,2304) conv1 | [2304,3328) conv2 | [3328,3334) bias
//   [3334,7430) x -> xb   (4096 blocks: BLN*DM/4 = 1048576 float4)
__global__ void __launch_bounds__(256) pack_all(
    const float* __restrict__ x,
    const float* __restrict__ Wq, const float* __restrict__ Wk,
    const float* __restrict__ Wv, const float* __restrict__ Wo,
    const float* __restrict__ gate_w, const float* __restrict__ conv1_w,
    const float* __restrict__ conv2_w,
    const float* __restrict__ bq, const float* __restrict__ bk,
    const float* __restrict__ bv,
    unsigned* __restrict__ xb,
    unsigned* __restrict__ wqkvT, unsigned* __restrict__ wopT,
    unsigned* __restrict__ wgb, unsigned* __restrict__ w1b,
    unsigned* __restrict__ w2b, float* __restrict__ bqkv)
{
    int bid = blockIdx.x;
    if (bid < 256) {
        tpose_blk(Wq, (__nv_bfloat16*)wqkvT, 0, bid);
    } else if (bid < 512) {
        tpose_blk(Wk, (__nv_bfloat16*)wqkvT, 512, bid - 256);
    } else if (bid < 768) {
        tpose_blk(Wv, (__nv_bfloat16*)wqkvT, 1024, bid - 512);
    } else if (bid < 1024) {
        tpose_blk(Wo, (__nv_bfloat16*)wopT, 0, bid - 768);
    } else if (bid < 1280) {
        cvt_blk((const float4*)gate_w, (uint2*)wgb, bid - 1024, DM*DM/4);
    } else if (bid < 2304) {
        cvt_blk((const float4*)conv1_w, (uint2*)w1b, bid - 1280, DM*DFF/4);
    } else if (bid < 3328) {
        cvt_blk((const float4*)conv2_w, (uint2*)w2b, bid - 2304, DM*DFF/4);
    } else if (bid < 3334) {
        int i = (bid - 3328) * 256 + threadIdx.x;
        if (i < QKVN)
            bqkv[i] = i < 512 ? bq[i] : (i < 1024 ? bk[i - 512] : bv[i - 1024]);
    } else {
        cvt_blk((const float4*)x, (uint2*)xb, bid - 3334, BLN*DM/4);
    }
}

__global__ void __launch_bounds__(256) vpack(const __nv_bfloat16* __restrict__ qkv,
                                             unsigned* __restrict__ vp)
{
    int i = blockIdx.x * 256 + threadIdx.x;
    int c = i & 511, jr = (i >> 9) & 511, b = i >> 18;
    const __nv_bfloat16* v0 = qkv + ((size_t)(b * 1024 + 2 * jr)) * QKVN + 1024 + c;
    __nv_bfloat162 w;
    w.x = v0[0];
    w.y = v0[QKVN];
    vp[i] = *(unsigned*)&w;
}

// ---------------- bf16 tensor-core GEMM, cp.async + ldmatrix ------------------
// issue(c+3) hoisted right after the leading barrier (deeper prefetch; safe:
// buffer (c+3)&3 was last read in chunk c-1, fenced by this barrier).
template<int BM, int BN, int EPI, bool TRANSB, bool OUTBF>
__global__ void __launch_bounds__(256, 2) gemm_bf(
    const unsigned* __restrict__ A, const unsigned* __restrict__ B,
    const float* __restrict__ bias, const float* __restrict__ aux,
    const float* __restrict__ scale, float alpha, void* __restrict__ Cv,
    int K, int ldaw, int ldbw, int ldc,
    long sAhi, long sAlo, long sBhi, long sBlo, long sChi, long sClo)
{
    constexpr int SK   = 20;
    constexpr int SBnt = BN + 8;
    constexpr int ASTG = BM * SK;
    constexpr int BSTG = TRANSB ? BN * SK : 16 * SBnt;
    constexpr int NF   = BN / 32;
    constexpr int NA   = BM * 4 / 256;
    constexpr int NBt  = BN * 4 / 256 ? BN * 4 / 256 : 1;
    constexpr int NBn  = 16 * (BN / 4) / 256 ? 16 * (BN / 4) / 256 : 1;

    extern __shared__ unsigned smem[];
    unsigned* As = smem;
    unsigned* Bs = smem + 4 * ASTG;

    const int z = blockIdx.z;
    const unsigned* Ab = A + (size_t)(z >> 3) * sAhi + (size_t)(z & 7) * sAlo
                           + (size_t)blockIdx.y * BM * ldaw;
    const unsigned* Bb = B + (size_t)(z >> 3) * sBhi + (size_t)(z & 7) * sBlo;
    if (TRANSB) Bb += (size_t)blockIdx.x * BN * ldbw;
    else        Bb += (size_t)blockIdx.x * BN;

    const int t = threadIdx.x;
    const int lane = t & 31, w = t >> 5;
    const int wr = w >> 2, wc = w & 3;
    const int r = lane >> 2, cq = lane & 3;
    const int mB = wr * 64, nB = wc * (BN / 4);

    const uint32_t smem_u = s2u(smem);
    const uint32_t laneA4 = (((lane & 15) * SK) + ((lane >> 4) << 2)) << 2;
    const uint32_t laneB4 = (((lane & 7) * SK) + (((lane >> 3) & 1) << 2)) << 2;

    const int NC = K >> 5;

    auto issue = [&](int s) {
        if (s < NC) {
            const int k0w = s << 4;
            unsigned* Ad = As + (s & 3) * ASTG;
#pragma unroll
            for (int i = 0; i < NA; i++) {
                int cid = t + i * 256;
                int row = cid >> 2, jw = (cid & 3) * 4;
                cpa16(Ad + row * SK + jw, Ab + (size_t)row * ldaw + k0w + jw);
            }
            unsigned* Bd = Bs + (s & 3) * BSTG;
            if (TRANSB) {
#pragma unroll
                for (int i = 0; i < NBt; i++) {
                    int cid = t + i * 256;
                    int row = cid >> 2, jw = (cid & 3) * 4;
                    cpa16(Bd + row * SK + jw, Bb + (size_t)row * ldbw + k0w + jw);
                }
            } else {
#pragma unroll
                for (int i = 0; i < NBn; i++) {
                    int cid = t + i * 256;
                    int kr = cid / (BN / 4), n4 = (cid % (BN / 4)) * 4;
                    cpa16(Bd + kr * SBnt + n4, Bb + (size_t)(k0w + kr) * ldbw + n4);
                }
            }
        }
        cpa_commit();
    };

    float acc[4][NF][4];
#pragma unroll
    for (int i = 0; i < 4; i++)
#pragma unroll
        for (int j = 0; j < NF; j++)
#pragma unroll
            for (int e = 0; e < 4; e++) acc[i][j][e] = 0.f;

    issue(0); issue(1); issue(2);

    for (int c = 0; c < NC; c++) {
        cpa_wait<2>();
        __syncthreads();
        issue(c + 3);
        const unsigned* Bc = Bs + (c & 3) * BSTG;
#pragma unroll
        for (int ks = 0; ks < 2; ks++) {
            const int kw = ks * 8;
            unsigned af[4][4], bf[NF][2];
            uint32_t abase = smem_u + (((c & 3) * ASTG + mB * SK + kw) << 2) + laneA4;
#pragma unroll
            for (int mf = 0; mf < 4; mf++)
                ldsm_x4(af[mf], abase + ((mf * 16 * SK) << 2));
            if (TRANSB) {
                uint32_t bbase = smem_u +
                    ((4 * ASTG + (c & 3) * BSTG + nB * SK + kw) << 2) + laneB4;
#pragma unroll
                for (int nf = 0; nf < NF; nf++)
                    ldsm_x2(bf[nf], bbase + ((nf * 8 * SK) << 2));
            } else {
#pragma unroll
                for (int nf = 0; nf < NF; nf++) {
                    const unsigned* bp = Bc + (kw + cq) * SBnt + nB + nf * 8 + r;
                    bf[nf][0] = bp[0];
                    bf[nf][1] = bp[4 * SBnt];
                }
            }
#pragma unroll
            for (int mf = 0; mf < 4; mf++)
#pragma unroll
                for (int nf = 0; nf < NF; nf++)
                    mma_bf16(acc[mf][nf], af[mf], bf[nf]);
        }
    }

    float scv = 1.f;
    if constexpr (EPI == 1 || EPI == 4) scv = *scale;
    float* Cf = (float*)Cv;
    unsigned* Cw = (unsigned*)Cv;
    const size_t cOff = (size_t)(z >> 3) * sChi + (size_t)(z & 7) * sClo;
    const int rowBase = blockIdx.y * BM + mB;
    const int colBase = blockIdx.x * BN + nB;
#pragma unroll
    for (int mf = 0; mf < 4; mf++) {
#pragma unroll
        for (int nf = 0; nf < NF; nf++) {
            int n = colBase + nf * 8 + 2 * cq;
#pragma unroll
            for (int h = 0; h < 2; h++) {
                int m = rowBase + mf * 16 + r + 8 * h;
                size_t idx = (size_t)m * ldc + n;
                float v0 = acc[mf][nf][2 * h + 0] * alpha;
                float v1 = acc[mf][nf][2 * h + 1] * alpha;
                if constexpr (EPI == 0) { v0 += bias[n]; v1 += bias[n + 1]; }
                else if constexpr (EPI == 1) {
                    v0 = aux[idx]     + scv * (v0 + bias[n]);
                    v1 = aux[idx + 1] + scv * (v1 + bias[n + 1]);
                } else if constexpr (EPI == 2) {
                    v0 = aux[idx]     / (1.f + expf(-(v0 + bias[n])));
                    v1 = aux[idx + 1] / (1.f + expf(-(v1 + bias[n + 1])));
                } else if constexpr (EPI == 3) {
                    v0 = fmaxf(v0, 0.f); v1 = fmaxf(v1, 0.f);
                } else if constexpr (EPI == 4) {
                    v0 = aux[idx]     + scv * v0;
                    v1 = aux[idx + 1] + scv * v1;
                }
                if constexpr (OUTBF) {
                    Cw[(cOff + idx) >> 1] = pack2bf(v0, v1);
                } else {
                    float2 o = { v0, v1 };
                    *(float2*)&Cf[cOff + idx] = o;
                }
            }
        }
    }
}

// ---------------- fused scores + softmax (256 threads, 8 warps) ---------------
#define SK2 36
#define SCSM ((1024 + 32) * SK2 * 4 + 32 * 8 * 4 * 2)

__global__ void __launch_bounds__(256, 1) scores_sm(
    const unsigned* __restrict__ qkv, float* __restrict__ attn,
    unsigned* __restrict__ pbf)
{
    extern __shared__ unsigned sm[];
    unsigned* Ks = sm;
    unsigned* Qs = sm + 1024 * SK2;
    float* smax  = (float*)(sm + (1024 + 32) * SK2);
    float* ssum  = smax + 32 * 8;

    const int bh = blockIdx.y, b = bh >> 3, h = bh & 7;
    const int i0 = blockIdx.x * 32;
    const int tid = threadIdx.x;

    const unsigned* qbase = qkv + (size_t)(b * 1024 + i0) * 768 + h * 32;
    const unsigned* kbase = qkv + (size_t)b * 1024 * 768 + 256 + h * 32;

#pragma unroll
    for (int i = 0; i < 32; i++) {
        int cid = tid + i * 256;
        int row = cid >> 3, jw = (cid & 7) * 4;
        cpa16(Ks + row * SK2 + jw, kbase + (size_t)row * 768 + jw);
    }
    {
        int row = tid >> 3, jw = (tid & 7) * 4;
        cpa16(Qs + row * SK2 + jw, qbase + (size_t)row * 768 + jw);
    }
    cpa_commit();
    cpa_wait<0>();
    __syncthreads();

    const int lane = tid & 31, w = tid >> 5;
    const int r = lane >> 2, cq = lane & 3;
    const uint32_t smem_u = s2u(sm);
    const uint32_t laneA4 = (((lane & 15) * SK2) + ((lane >> 4) << 2)) << 2;
    const uint32_t laneB4 = (((lane & 7) * SK2) + (((lane >> 3) & 1) << 2)) << 2;

    float acc[2][16][4];
#pragma unroll
    for (int mf = 0; mf < 2; mf++)
#pragma unroll
        for (int nf = 0; nf < 16; nf++)
#pragma unroll
            for (int e = 0; e < 4; e++) acc[mf][nf][e] = 0.f;

#pragma unroll
    for (int kc = 0; kc < 4; kc++) {
        const int kw = kc * 8;
        unsigned af[2][4];
        uint32_t ab = smem_u + ((1024 * SK2 + kw) << 2) + laneA4;
        ldsm_x4(af[0], ab);
        ldsm_x4(af[1], ab + ((16 * SK2) << 2));
#pragma unroll
        for (int nf = 0; nf < 16; nf++) {
            unsigned bf[2];
            uint32_t bb = smem_u + (((w * 128 + nf * 8) * SK2 + kw) << 2) + laneB4;
            ldsm_x2(bf, bb);
            mma_bf16(acc[0][nf], af[0], bf);
            mma_bf16(acc[1][nf], af[1], bf);
        }
    }

#pragma unroll
    for (int mf = 0; mf < 2; mf++)
#pragma unroll
        for (int nf = 0; nf < 16; nf++)
#pragma unroll
            for (int e = 0; e < 4; e++) acc[mf][nf][e] *= 0.125f;

#pragma unroll
    for (int mf = 0; mf < 2; mf++)
#pragma unroll
        for (int hh = 0; hh < 2; hh++) {
            float m = -3.4e38f;
#pragma unroll
            for (int nf = 0; nf < 16; nf++)
                m = fmaxf(m, fmaxf(acc[mf][nf][2 * hh], acc[mf][nf][2 * hh + 1]));
            m = fmaxf(m, __shfl_xor_sync(~0u, m, 1));
            m = fmaxf(m, __shfl_xor_sync(~0u, m, 2));
            if (cq == 0) smax[(mf * 16 + hh * 8 + r) * 8 + w] = m;
        }
    __syncthreads();
    float gmax[4];
#pragma unroll
    for (int mf = 0; mf < 2; mf++)
#pragma unroll
        for (int hh = 0; hh < 2; hh++) {
            const float* p = smax + (mf * 16 + hh * 8 + r) * 8;
            float m = p[0];
#pragma unroll
            for (int j = 1; j < 8; j++) m = fmaxf(m, p[j]);
            gmax[mf * 2 + hh] = m;
        }

#pragma unroll
    for (int mf = 0; mf < 2; mf++)
#pragma unroll
        for (int hh = 0; hh < 2; hh++) {
            float gm = gmax[mf * 2 + hh];
            float s = 0.f;
#pragma unroll
            for (int nf = 0; nf < 16; nf++) {
                float e0 = __expf(acc[mf][nf][2 * hh]     - gm);
                float e1 = __expf(acc[mf][nf][2 * hh + 1] - gm);
                acc[mf][nf][2 * hh]     = e0;
                acc[mf][nf][2 * hh + 1] = e1;
                s += e0 + e1;
            }
            s += __shfl_xor_sync(~0u, s, 1);
            s += __shfl_xor_sync(~0u, s, 2);
            if (cq == 0) ssum[(mf * 16 + hh * 8 + r) * 8 + w] = s;
        }
    __syncthreads();
    float ginv[4];
#pragma unroll
    for (int mf = 0; mf < 2; mf++)
#pragma unroll
        for (int hh = 0; hh < 2; hh++) {
            const float* p = ssum + (mf * 16 + hh * 8 + r) * 8;
            float s = 0.f;
#pragma unroll
            for (int j = 0; j < 8; j++) s += p[j];
            ginv[mf * 2 + hh] = 1.f / s;
        }

#pragma unroll
    for (int mf = 0; mf < 2; mf++)
#pragma unroll
        for (int hh = 0; hh < 2; hh++) {
            const int arow = mf * 16 + hh * 8 + r;
            const size_t grow = (size_t)bh * 1024 + i0 + arow;
            const float inv = ginv[mf * 2 + hh];
#pragma unroll
            for (int nf = 0; nf < 16; nf++) {
                int col = w * 128 + nf * 8 + 2 * cq;
                float v0 = acc[mf][nf][2 * hh]     * inv;
                float v1 = acc[mf][nf][2 * hh + 1] * inv;
                float2 o = { v0, v1 };
                *(float2*)&attn[grow * 1024 + col] = o;
                pbf[grow * 512 + (col >> 1)] = pack2bf(v0, v1);
            }
        }
}

// ---------------- partial column means ----------------------------------------
__global__ void __launch_bounds__(512) col_mean2(const float* __restrict__ x,
                                                 float* __restrict__ part)
{
    int chunk = blockIdx.x, b = blockIdx.y, d = threadIdx.x;
    const float* p = x + ((size_t)b * LL + chunk * 128) * DM + d;
    float s = 0.f;
#pragma unroll 8
    for (int t = 0; t < 128; t++) s += p[(size_t)t * DM];
    part[(b * 8 + chunk) * DM + d] = s;
}

// ---------------- kernel-size predictor ----------------------------------------
__global__ void __launch_bounds__(256) kernel_pred(const float* __restrict__ part,
                                                   const float* __restrict__ w1,
                                                   const float* __restrict__ b1,
                                                   const float* __restrict__ w2,
                                                   const float* __restrict__ b2,
                                                   const float* __restrict__ tw,
                                                   float* __restrict__ wout,
                                                   int* __restrict__ kout)
{
    int b = blockIdx.x, j = threadIdx.x;
    __shared__ float xs[DM];
    float s0 = 0.f, s1 = 0.f;
#pragma unroll
    for (int c = 0; c < 8; c++) {
        s0 += part[(b * 8 + c) * DM + j];
        s1 += part[(b * 8 + c) * DM + j + 256];
    }
    xs[j]       = s0 * (1.f / 1024.f);
    xs[j + 256] = s1 * (1.f / 1024.f);
    __syncthreads();
    float hj = b1[j];
#pragma unroll 4
    for (int d = 0; d < DM; d++) hj = fmaf(xs[d], w1[d*256 + j], hj);
    hj = fmaxf(hj, 0.f) * w2[j];
    __shared__ float red[256];
    red[j] = hj;
    __syncthreads();
    for (int s = 128; s; s >>= 1) { if (j < s) red[j] += red[j + s]; __syncthreads(); }
    if (j == 0) {
        float sv = 1.f / (1.f + expf(-(red[0] + b2[0])));
        int kk = (int)rintf(sv * 45.f + 5.f);
        kk = max(5, min(kk, MAXK));
        kout[b] = kk;
        float m = -3.4e38f;
        for (int i = 0; i < kk; i++) m = fmaxf(m, tw[i]);
        float e[MAXK], su = 0.f;
        for (int i = 0; i < kk; i++) { e[i] = expf(tw[i] - m); su += e[i]; }
        float inv = 1.f / su;
        for (int i = 0; i < MAXK; i++) wout[b*MAXK + i] = (i < kk) ? e[i] * inv : 0.f;
    }
}

// ---------------- smem-tiled decomp --------------------------------------------
#define DROWS 180
#define DPITCH 132
__global__ void __launch_bounds__(256) decomp_t(const float* __restrict__ x,
                                                const float* __restrict__ w,
                                                const int* __restrict__ kk,
                                                float* __restrict__ out,
                                                unsigned* __restrict__ obf)
{
    extern __shared__ float smf[];
    __shared__ float ws[MAXK];
    const int b = blockIdx.z, t0 = blockIdx.x * 128, d0 = blockIdx.y * 128;
    const int k = kk[b];
    const int tid = threadIdx.x;
    if (tid < MAXK) ws[tid] = w[b * MAXK + tid];
    const int s0 = t0 - (k >> 1);
    const int L  = 127 + k;
    const float* xb = x + (size_t)b * LL * DM;
    const int c4 = tid & 31;
    for (int j = tid >> 5; j < L; j += 8) {
        int src = s0 + j;
        src = src < 0 ? 0 : (src > LL - 1 ? LL - 1 : src);
        *(float4*)&smf[j * DPITCH + c4 * 4] =
            *(const float4*)(xb + (size_t)src * DM + d0 + c4 * 4);
    }
    __syncthreads();
    const int trow = tid >> 5;
    for (int tt = trow; tt < 128; tt += 8) {
        float4 acc = { 0.f, 0.f, 0.f, 0.f };
        for (int i = 0; i < k; i++) {
            float wi = ws[i];
            float4 xv = *(const float4*)&smf[(tt + i) * DPITCH + c4 * 4];
            acc.x = fmaf(wi, xv.x, acc.x); acc.y = fmaf(wi, xv.y, acc.y);
            acc.z = fmaf(wi, xv.z, acc.z); acc.w = fmaf(wi, xv.w, acc.w);
        }
        size_t o = (size_t)(b * LL + t0 + tt) * DM + d0 + c4 * 4;
        float4 xo = *(const float4*)(x + o);
        xo.x -= acc.x; xo.y -= acc.y; xo.z -= acc.z; xo.w -= acc.w;
        *(float4*)(out + o) = xo;
        if (obf) {
            uint2 u = { pack2bf(xo.x, xo.y), pack2bf(xo.z, xo.w) };
            *(uint2*)&obf[(size_t)(b * LL + t0 + tt) * 256 + ((d0 >> 1) + c4 * 2)] = u;
        }
    }
}
#define DSMEM (DROWS * DPITCH * 4)

// -----------------------------------------------------------------------------
static inline int smem_sz(int BM, int BN, bool transB) {
    int astg = BM * 20;
    int bstg = transB ? BN * 20 : 16 * (BN + 8);
    return 4 * (astg + bstg) * 4;
}

extern "C" void kernel_launch(void* const* d_in, const int* in_sizes, int n_in,
                              void* d_out, int out_size)
{
    const float* x       = (const float*)d_in[0];
    const float* Wq      = (const float*)d_in[1];
    const float* bq      = (const float*)d_in[2];
    const float* Wk      = (const float*)d_in[3];
    const float* bk      = (const float*)d_in[4];
    const float* Wv      = (const float*)d_in[5];
    const float* bv      = (const float*)d_in[6];
    const float* Wo      = (const float*)d_in[7];
    const float* bo      = (const float*)d_in[8];
    const float* gate_w  = (const float*)d_in[9];
    const float* gate_b  = (const float*)d_in[10];
    const float* conv1_w = (const float*)d_in[11];
    const float* conv2_w = (const float*)d_in[12];
    const float* tw1     = (const float*)d_in[13];
    const float* kp1_w1  = (const float*)d_in[14];
    const float* kp1_b1  = (const float*)d_in[15];
    const float* kp1_w2  = (const float*)d_in[16];
    const float* kp1_b2  = (const float*)d_in[17];
    const float* tw2     = (const float*)d_in[18];
    const float* kp2_w1  = (const float*)d_in[19];
    const float* kp2_b1  = (const float*)d_in[20];
    const float* kp2_w2  = (const float*)d_in[21];
    const float* kp2_b2  = (const float*)d_in[22];
    const float* attn_sc = (const float*)d_in[23];
    const float* ffn_sc  = (const float*)d_in[24];

    float* res  = (float*)d_out;
    float* attn = (float*)d_out + (size_t)BB*LL*DM;

    unsigned *qkvbf, *pbf, *vp, *t0b, *x2b, *ggb, *hidb, *xb;
    unsigned *wqkvT, *wopT, *wgb, *w1b, *w2b;
    float *bqkv, *x1, *x2, *xg, *wb;
    int* kb;
    cudaGetSymbolAddress((void**)&qkvbf, g_qkvbf);
    cudaGetSymbolAddress((void**)&pbf,   g_pbf);
    cudaGetSymbolAddress((void**)&vp,    g_vp);
    cudaGetSymbolAddress((void**)&t0b,   g_t0b);
    cudaGetSymbolAddress((void**)&x2b,   g_x2b);
    cudaGetSymbolAddress((void**)&ggb,   g_ggb);
    cudaGetSymbolAddress((void**)&hidb,  g_hidb);
    cudaGetSymbolAddress((void**)&xb,    g_xb);
    cudaGetSymbolAddress((void**)&wqkvT, g_wqkvT);
    cudaGetSymbolAddress((void**)&wopT,  g_wopT);
    cudaGetSymbolAddress((void**)&wgb,   g_wgb);
    cudaGetSymbolAddress((void**)&w1b,   g_w1b);
    cudaGetSymbolAddress((void**)&w2b,   g_w2b);
    cudaGetSymbolAddress((void**)&bqkv,  g_bqkv);
    cudaGetSymbolAddress((void**)&x1,    g_x1);
    cudaGetSymbolAddress((void**)&x2,    g_x2);
    cudaGetSymbolAddress((void**)&xg,    g_xg);
    cudaGetSymbolAddress((void**)&wb,    g_w);
    cudaGetSymbolAddress((void**)&kb,    g_kk);

    const int szT  = smem_sz(128, 128, true);   // 81920
    const int szAV = smem_sz(128,  64, false);  // 59392

    cudaFuncSetAttribute((const void*)gemm_bf<128,128,0,true ,true >, cudaFuncAttributeMaxDynamicSharedMemorySize, szT);
    cudaFuncSetAttribute((const void*)gemm_bf<128, 64,5,false,true >, cudaFuncAttributeMaxDynamicSharedMemorySize, szAV);
    cudaFuncSetAttribute((const void*)gemm_bf<128,128,1,true ,false>, cudaFuncAttributeMaxDynamicSharedMemorySize, szT);
    cudaFuncSetAttribute((const void*)gemm_bf<128,128,2,true ,true >, cudaFuncAttributeMaxDynamicSharedMemorySize, szT);
    cudaFuncSetAttribute((const void*)gemm_bf<128,128,3,true ,true >, cudaFuncAttributeMaxDynamicSharedMemorySize, szT);
    cudaFuncSetAttribute((const void*)gemm_bf<128,128,4,true ,false>, cudaFuncAttributeMaxDynamicSharedMemorySize, szT);
    cudaFuncSetAttribute((const void*)scores_sm, cudaFuncAttributeMaxDynamicSharedMemorySize, SCSM);
    cudaFuncSetAttribute((const void*)decomp_t, cudaFuncAttributeMaxDynamicSharedMemorySize, DSMEM);

    const dim3 blk(256);

    // ---- pack / convert: single launch (3334 weight/bias blocks + 4096 x blocks) ----
    pack_all<<<7430, 256>>>(x, Wq, Wk, Wv, Wo, gate_w, conv1_w, conv2_w,
                            bq, bk, bv, xb, wqkvT, wopT, wgb, w1b, w2b, bqkv);

    // QKV: [8192,1536] = xb @ wqkvT^T  (bf16 out)
    gemm_bf<128,128,0,true,true><<<dim3(QKVN/128, BLN/128, 1), blk, szT>>>(
        xb, wqkvT, bqkv, nullptr, nullptr, 1.f, qkvbf,
        DM, 256, 256, QKVN, 0,0,0,0,0,0);

    vpack<<<(8*512*512)/256, 256>>>((const __nv_bfloat16*)qkvbf, vp);

    // fused scores + softmax: writes attn (fp32) + pbf (bf16)
    scores_sm<<<dim3(LL/32, BB*HH), blk, SCSM>>>(qkvbf, attn, pbf);

    // AV: t0 = p @ v  (bf16 out)
    gemm_bf<128,64,5,false,true><<<dim3(1, LL/128, BB*HH), blk, szAV>>>(
        pbf, vp, nullptr, nullptr, nullptr, 1.f, t0b,
        LL, 512, 512, DM,
        (long)8*LL*512, (long)LL*512, 262144, 64, (long)LL*DM, 64);

    // out proj + residual (fp32): x1 = x + attn_sc*(t0 @ Wo + bo)
    gemm_bf<128,128,1,true,false><<<dim3(DM/128, BLN/128, 1), blk, szT>>>(
        t0b, wopT, bo, x, attn_sc, 1.f, x1,
        DM, 256, 256, DM, 0,0,0,0,0,0);

    // decomp 1
    col_mean2<<<dim3(8, BB), 512>>>(x1, xg);
    kernel_pred<<<BB, 256>>>(xg, kp1_w1, kp1_b1, kp1_w2, kp1_b2, tw1, wb, kb);
    decomp_t<<<dim3(8, 4, BB), 256, DSMEM>>>(x1, wb, kb, x2, x2b);

    // FFN
    gemm_bf<128,128,2,true,true><<<dim3(DM/128, BLN/128, 1), blk, szT>>>(
        x2b, wgb, gate_b, x2, nullptr, 1.f, ggb,
        DM, 256, 256, DM, 0,0,0,0,0,0);
    gemm_bf<128,128,3,true,true><<<dim3(DFF/128, BLN/128, 1), blk, szT>>>(
        ggb, w1b, nullptr, nullptr, nullptr, 1.f, hidb,
        DM, 256, 256, DFF, 0,0,0,0,0,0);
    gemm_bf<128,128,4,true,false><<<dim3(DM/128, BLN/128, 1), blk, szT>>>(
        hidb, w2b, nullptr, x2, ffn_sc, 1.f, x1,
        DFF, 1024, 1024, DM, 0,0,0,0,0,0);

    // decomp 2 -> res
    col_mean2<<<dim3(8, BB), 512>>>(x1, xg);
    kernel_pred<<<BB, 256>>>(xg, kp2_w1, kp2_b1, kp2_w2, kp2_b2, tw2, wb, kb);
    decomp_t<<<dim3(8, 4, BB), 256, DSMEM>>>(x1, wb, kb, res, nullptr);
}

// round 15
// speedup vs baseline: 1.0090x; 1.0090x over previous
#include <cuda_runtime.h>
#include <cuda_bf16.h>
#include <math.h>
#include <stdint.h>

#define BB 8
#define LL 1024
#define DM 512
#define HH 8
#define HD 64
#define DFF 2048
#define BLN (BB*LL)
#define MAXK 50
#define QKVN 1536

// ---------------- scratch (device globals; no allocations allowed) ----------
__device__ __align__(16) unsigned g_qkvbf[(size_t)BLN*768];
__device__ __align__(16) unsigned g_pbf[(size_t)64*1024*512];
__device__ __align__(16) unsigned g_vp[(size_t)8*512*512];
__device__ __align__(16) unsigned g_t0b[BLN*256];
__device__ __align__(16) unsigned g_x2b[BLN*256];
__device__ __align__(16) unsigned g_ggb[BLN*256];
__device__ __align__(16) unsigned g_hidb[(size_t)BLN*1024];
__device__ __align__(16) unsigned g_xb[BLN*256];
__device__ __align__(16) unsigned g_wqkvT[QKVN*256];
__device__ __align__(16) unsigned g_wopT[512*256];
__device__ __align__(16) unsigned g_wgb[512*256];
__device__ __align__(16) unsigned g_w1b[2048*256];
__device__ __align__(16) unsigned g_w2b[512*1024];
__device__ float g_bqkv[QKVN];
__device__ float g_x1[BLN*DM];
__device__ float g_x2[BLN*DM];
__device__ float g_xg[BB*8*DM];
__device__ float g_w [BB*MAXK];
__device__ int   g_kk[BB];

// ---------------- helpers ----------------------------------------------------
__device__ __forceinline__ unsigned pack2bf(float a, float b) {
    __nv_bfloat162 w;
    w.x = __float2bfloat16_rn(a);
    w.y = __float2bfloat16_rn(b);
    return *(unsigned*)&w;
}

__device__ __forceinline__ void mma_bf16(float c[4], const unsigned a[4], const unsigned b[2]) {
    asm volatile(
        "mma.sync.aligned.m16n8k16.row.col.f32.bf16.bf16.f32 "
        "{%0,%1,%2,%3},{%4,%5,%6,%7},{%8,%9},{%0,%1,%2,%3};"
        : "+f"(c[0]), "+f"(c[1]), "+f"(c[2]), "+f"(c[3])
        : "r"(a[0]), "r"(a[1]), "r"(a[2]), "r"(a[3]), "r"(b[0]), "r"(b[1]));
}

__device__ __forceinline__ void ldsm_x4(unsigned r[4], uint32_t addr) {
    asm volatile("ldmatrix.sync.aligned.m8n8.x4.shared.b16 {%0,%1,%2,%3}, [%4];"
        : "=r"(r[0]), "=r"(r[1]), "=r"(r[2]), "=r"(r[3]) : "r"(addr));
}
__device__ __forceinline__ void ldsm_x2(unsigned r[2], uint32_t addr) {
    asm volatile("ldmatrix.sync.aligned.m8n8.x2.shared.b16 {%0,%1}, [%2];"
        : "=r"(r[0]), "=r"(r[1]) : "r"(addr));
}

__device__ __forceinline__ void cpa16(void* dst, const void* src) {
    unsigned d = (unsigned)__cvta_generic_to_shared(dst);
    asm volatile("cp.async.cg.shared.global [%0], [%1], 16;" :: "r"(d), "l"(src));
}
__device__ __forceinline__ void cpa_commit() { asm volatile("cp.async.commit_group;"); }
template<int N>
__device__ __forceinline__ void cpa_wait() { asm volatile("cp.async.wait_group %0;" :: "n"(N)); }
__device__ __forceinline__ uint32_t s2u(const void* p) {
    return (uint32_t)__cvta_generic_to_shared(p);
}
__device__ __forceinline__ void stcs2(float* p, float a, float b) {
    float2 v = { a, b };
    asm volatile("st.global.cs.v2.f32 [%0], {%1, %2};" :: "l"(p), "f"(v.x), "f"(v.y) : "memory");
}

// ---------------- merged pack kernel -------------------------------------------
__device__ __forceinline__ void tpose_blk(const float* __restrict__ W,
                                          __nv_bfloat16* __restrict__ out,
                                          int rowOff, int idx)
{
    __shared__ float t[32][33];
    int k0 = (idx & 15) * 32, n0 = (idx >> 4) * 32;
    int tx = threadIdx.x & 31, ty = threadIdx.x >> 5;
#pragma unroll
    for (int i = 0; i < 4; i++)
        t[ty + 8 * i][tx] = W[(size_t)(k0 + ty + 8 * i) * 512 + n0 + tx];
    __syncthreads();
#pragma unroll
    for (int i = 0; i < 4; i++)
        out[(size_t)(rowOff + n0 + ty + 8 * i) * 512 + k0 + tx] =
            __float2bfloat16_rn(t[tx][ty + 8 * i]);
}
__device__ __forceinline__ void cvt_blk(const float4* __restrict__ src,
                                        uint2* __restrict__ dst, int idx, int n4)
{
    int i = idx * 256 + threadIdx.x;
    if (i < n4) {
        float4 v = src[i];
        uint2 u = { pack2bf(v.x, v.y), pack2bf(v.z, v.w) };
        dst[i] = u;
    }
}

__global__ void __launch_bounds__(256) pack_all(
    const float* __restrict__ x,
    const float* __restrict__ Wq, const float* __restrict__ Wk,
    const float* __restrict__ Wv, const float* __restrict__ Wo,
    const float* __restrict__ gate_w, const float* __restrict__ conv1_w,
    const float* __restrict__ conv2_w,
    const float* __restrict__ bq, const float* __restrict__ bk,
    const float* __restrict__ bv,
    unsigned* __restrict__ xb,
    unsigned* __restrict__ wqkvT, unsigned* __restrict__ wopT,
    unsigned* __restrict__ wgb, unsigned* __restrict__ w1b,
    unsigned* __restrict__ w2b, float* __restrict__ bqkv)
{
    int bid = blockIdx.x;
    if (bid < 256) {
        tpose_blk(Wq, (__nv_bfloat16*)wqkvT, 0, bid);
    } else if (bid < 512) {
        tpose_blk(Wk, (__nv_bfloat16*)wqkvT, 512, bid - 256);
    } else if (bid < 768) {
        tpose_blk(Wv, (__nv_bfloat16*)wqkvT, 1024, bid - 512);
    } else if (bid < 1024) {
        tpose_blk(Wo, (__nv_bfloat16*)wopT, 0, bid - 768);
    } else if (bid < 1280) {
        cvt_blk((const float4*)gate_w, (uint2*)wgb, bid - 1024, DM*DM/4);
    } else if (bid < 2304) {
        cvt_blk((const float4*)conv1_w, (uint2*)w1b, bid - 1280, DM*DFF/4);
    } else if (bid < 3328) {
        cvt_blk((const float4*)conv2_w, (uint2*)w2b, bid - 2304, DM*DFF/4);
    } else if (bid < 3334) {
        int i = (bid - 3328) * 256 + threadIdx.x;
        if (i < QKVN)
            bqkv[i] = i < 512 ? bq[i] : (i < 1024 ? bk[i - 512] : bv[i - 1024]);
    } else {
        cvt_blk((const float4*)x, (uint2*)xb, bid - 3334, BLN*DM/4);
    }
}

__global__ void __launch_bounds__(256) vpack(const __nv_bfloat16* __restrict__ qkv,
                                             unsigned* __restrict__ vp)
{
    int i = blockIdx.x * 256 + threadIdx.x;
    int c = i & 511, jr = (i >> 9) & 511, b = i >> 18;
    const __nv_bfloat16* v0 = qkv + ((size_t)(b * 1024 + 2 * jr)) * QKVN + 1024 + c;
    __nv_bfloat162 w;
    w.x = v0[0];
    w.y = v0[QKVN];
    vp[i] = *(unsigned*)&w;
}

// ---------------- bf16 tensor-core GEMM (round-12 pipeline order) -------------
template<int BM, int BN, int EPI, bool TRANSB, bool OUTBF>
__global__ void __launch_bounds__(256, 2) gemm_bf(
    const unsigned* __restrict__ A, const unsigned* __restrict__ B,
    const float* __restrict__ bias, const float* __restrict__ aux,
    const float* __restrict__ scale, float alpha, void* __restrict__ Cv,
    int K, int ldaw, int ldbw, int ldc,
    long sAhi, long sAlo, long sBhi, long sBlo, long sChi, long sClo)
{
    constexpr int SK   = 20;
    constexpr int SBnt = BN + 8;
    constexpr int ASTG = BM * SK;
    constexpr int BSTG = TRANSB ? BN * SK : 16 * SBnt;
    constexpr int NF   = BN / 32;
    constexpr int NA   = BM * 4 / 256;
    constexpr int NBt  = BN * 4 / 256 ? BN * 4 / 256 : 1;
    constexpr int NBn  = 16 * (BN / 4) / 256 ? 16 * (BN / 4) / 256 : 1;

    extern __shared__ unsigned smem[];
    unsigned* As = smem;
    unsigned* Bs = smem + 4 * ASTG;

    const int z = blockIdx.z;
    const unsigned* Ab = A + (size_t)(z >> 3) * sAhi + (size_t)(z & 7) * sAlo
                           + (size_t)blockIdx.y * BM * ldaw;
    const unsigned* Bb = B + (size_t)(z >> 3) * sBhi + (size_t)(z & 7) * sBlo;
    if (TRANSB) Bb += (size_t)blockIdx.x * BN * ldbw;
    else        Bb += (size_t)blockIdx.x * BN;

    const int t = threadIdx.x;
    const int lane = t & 31, w = t >> 5;
    const int wr = w >> 2, wc = w & 3;
    const int r = lane >> 2, cq = lane & 3;
    const int mB = wr * 64, nB = wc * (BN / 4);

    const uint32_t smem_u = s2u(smem);
    const uint32_t laneA4 = (((lane & 15) * SK) + ((lane >> 4) << 2)) << 2;
    const uint32_t laneB4 = (((lane & 7) * SK) + (((lane >> 3) & 1) << 2)) << 2;

    const int NC = K >> 5;

    auto issue = [&](int s) {
        if (s < NC) {
            const int k0w = s << 4;
            unsigned* Ad = As + (s & 3) * ASTG;
#pragma unroll
            for (int i = 0; i < NA; i++) {
                int cid = t + i * 256;
                int row = cid >> 2, jw = (cid & 3) * 4;
                cpa16(Ad + row * SK + jw, Ab + (size_t)row * ldaw + k0w + jw);
            }
            unsigned* Bd = Bs + (s & 3) * BSTG;
            if (TRANSB) {
#pragma unroll
                for (int i = 0; i < NBt; i++) {
                    int cid = t + i * 256;
                    int row = cid >> 2, jw = (cid & 3) * 4;
                    cpa16(Bd + row * SK + jw, Bb + (size_t)row * ldbw + k0w + jw);
                }
            } else {
#pragma unroll
                for (int i = 0; i < NBn; i++) {
                    int cid = t + i * 256;
                    int kr = cid / (BN / 4), n4 = (cid % (BN / 4)) * 4;
                    cpa16(Bd + kr * SBnt + n4, Bb + (size_t)(k0w + kr) * ldbw + n4);
                }
            }
        }
        cpa_commit();
    };

    float acc[4][NF][4];
#pragma unroll
    for (int i = 0; i < 4; i++)
#pragma unroll
        for (int j = 0; j < NF; j++)
#pragma unroll
            for (int e = 0; e < 4; e++) acc[i][j][e] = 0.f;

    issue(0); issue(1); issue(2);

    for (int c = 0; c < NC; c++) {
        cpa_wait<2>();
        __syncthreads();
        const unsigned* Bc = Bs + (c & 3) * BSTG;
#pragma unroll
        for (int ks = 0; ks < 2; ks++) {
            const int kw = ks * 8;
            unsigned af[4][4], bf[NF][2];
            uint32_t abase = smem_u + (((c & 3) * ASTG + mB * SK + kw) << 2) + laneA4;
#pragma unroll
            for (int mf = 0; mf < 4; mf++)
                ldsm_x4(af[mf], abase + ((mf * 16 * SK) << 2));
            if (TRANSB) {
                uint32_t bbase = smem_u +
                    ((4 * ASTG + (c & 3) * BSTG + nB * SK + kw) << 2) + laneB4;
#pragma unroll
                for (int nf = 0; nf < NF; nf++)
                    ldsm_x2(bf[nf], bbase + ((nf * 8 * SK) << 2));
            } else {
#pragma unroll
                for (int nf = 0; nf < NF; nf++) {
                    const unsigned* bp = Bc + (kw + cq) * SBnt + nB + nf * 8 + r;
                    bf[nf][0] = bp[0];
                    bf[nf][1] = bp[4 * SBnt];
                }
            }
#pragma unroll
            for (int mf = 0; mf < 4; mf++)
#pragma unroll
                for (int nf = 0; nf < NF; nf++)
                    mma_bf16(acc[mf][nf], af[mf], bf[nf]);
        }
        issue(c + 3);
    }

    float scv = 1.f;
    if constexpr (EPI == 1 || EPI == 4) scv = *scale;
    float* Cf = (float*)Cv;
    unsigned* Cw = (unsigned*)Cv;
    const size_t cOff = (size_t)(z >> 3) * sChi + (size_t)(z & 7) * sClo;
    const int rowBase = blockIdx.y * BM + mB;
    const int colBase = blockIdx.x * BN + nB;
#pragma unroll
    for (int mf = 0; mf < 4; mf++) {
#pragma unroll
        for (int nf = 0; nf < NF; nf++) {
            int n = colBase + nf * 8 + 2 * cq;
#pragma unroll
            for (int h = 0; h < 2; h++) {
                int m = rowBase + mf * 16 + r + 8 * h;
                size_t idx = (size_t)m * ldc + n;
                float v0 = acc[mf][nf][2 * h + 0] * alpha;
                float v1 = acc[mf][nf][2 * h + 1] * alpha;
                if constexpr (EPI == 0) { v0 += bias[n]; v1 += bias[n + 1]; }
                else if constexpr (EPI == 1) {
                    v0 = aux[idx]     + scv * (v0 + bias[n]);
                    v1 = aux[idx + 1] + scv * (v1 + bias[n + 1]);
                } else if constexpr (EPI == 2) {
                    v0 = aux[idx]     / (1.f + expf(-(v0 + bias[n])));
                    v1 = aux[idx + 1] / (1.f + expf(-(v1 + bias[n + 1])));
                } else if constexpr (EPI == 3) {
                    v0 = fmaxf(v0, 0.f); v1 = fmaxf(v1, 0.f);
                } else if constexpr (EPI == 4) {
                    v0 = aux[idx]     + scv * v0;
                    v1 = aux[idx + 1] + scv * v1;
                }
                if constexpr (OUTBF) {
                    Cw[(cOff + idx) >> 1] = pack2bf(v0, v1);
                } else {
                    float2 o = { v0, v1 };
                    *(float2*)&Cf[cOff + idx] = o;
                }
            }
        }
    }
}

// ---------------- fused scores + softmax (streaming attn store) ---------------
#define SK2 36
#define SCSM ((1024 + 32) * SK2 * 4 + 32 * 8 * 4 * 2)

__global__ void __launch_bounds__(256, 1) scores_sm(
    const unsigned* __restrict__ qkv, float* __restrict__ attn,
    unsigned* __restrict__ pbf)
{
    extern __shared__ unsigned sm[];
    unsigned* Ks = sm;
    unsigned* Qs = sm + 1024 * SK2;
    float* smax  = (float*)(sm + (1024 + 32) * SK2);
    float* ssum  = smax + 32 * 8;

    const int bh = blockIdx.y, b = bh >> 3, h = bh & 7;
    const int i0 = blockIdx.x * 32;
    const int tid = threadIdx.x;

    const unsigned* qbase = qkv + (size_t)(b * 1024 + i0) * 768 + h * 32;
    const unsigned* kbase = qkv + (size_t)b * 1024 * 768 + 256 + h * 32;

#pragma unroll
    for (int i = 0; i < 32; i++) {
        int cid = tid + i * 256;
        int row = cid >> 3, jw = (cid & 7) * 4;
        cpa16(Ks + row * SK2 + jw, kbase + (size_t)row * 768 + jw);
    }
    {
        int row = tid >> 3, jw = (tid & 7) * 4;
        cpa16(Qs + row * SK2 + jw, qbase + (size_t)row * 768 + jw);
    }
    cpa_commit();
    cpa_wait<0>();
    __syncthreads();

    const int lane = tid & 31, w = tid >> 5;
    const int r = lane >> 2, cq = lane & 3;
    const uint32_t smem_u = s2u(sm);
    const uint32_t laneA4 = (((lane & 15) * SK2) + ((lane >> 4) << 2)) << 2;
    const uint32_t laneB4 = (((lane & 7) * SK2) + (((lane >> 3) & 1) << 2)) << 2;

    float acc[2][16][4];
#pragma unroll
    for (int mf = 0; mf < 2; mf++)
#pragma unroll
        for (int nf = 0; nf < 16; nf++)
#pragma unroll
            for (int e = 0; e < 4; e++) acc[mf][nf][e] = 0.f;

#pragma unroll
    for (int kc = 0; kc < 4; kc++) {
        const int kw = kc * 8;
        unsigned af[2][4];
        uint32_t ab = smem_u + ((1024 * SK2 + kw) << 2) + laneA4;
        ldsm_x4(af[0], ab);
        ldsm_x4(af[1], ab + ((16 * SK2) << 2));
#pragma unroll
        for (int nf = 0; nf < 16; nf++) {
            unsigned bf[2];
            uint32_t bb = smem_u + (((w * 128 + nf * 8) * SK2 + kw) << 2) + laneB4;
            ldsm_x2(bf, bb);
            mma_bf16(acc[0][nf], af[0], bf);
            mma_bf16(acc[1][nf], af[1], bf);
        }
    }

#pragma unroll
    for (int mf = 0; mf < 2; mf++)
#pragma unroll
        for (int nf = 0; nf < 16; nf++)
#pragma unroll
            for (int e = 0; e < 4; e++) acc[mf][nf][e] *= 0.125f;

#pragma unroll
    for (int mf = 0; mf < 2; mf++)
#pragma unroll
        for (int hh = 0; hh < 2; hh++) {
            float m = -3.4e38f;
#pragma unroll
            for (int nf = 0; nf < 16; nf++)
                m = fmaxf(m, fmaxf(acc[mf][nf][2 * hh], acc[mf][nf][2 * hh + 1]));
            m = fmaxf(m, __shfl_xor_sync(~0u, m, 1));
            m = fmaxf(m, __shfl_xor_sync(~0u, m, 2));
            if (cq == 0) smax[(mf * 16 + hh * 8 + r) * 8 + w] = m;
        }
    __syncthreads();
    float gmax[4];
#pragma unroll
    for (int mf = 0; mf < 2; mf++)
#pragma unroll
        for (int hh = 0; hh < 2; hh++) {
            const float* p = smax + (mf * 16 + hh * 8 + r) * 8;
            float m = p[0];
#pragma unroll
            for (int j = 1; j < 8; j++) m = fmaxf(m, p[j]);
            gmax[mf * 2 + hh] = m;
        }

#pragma unroll
    for (int mf = 0; mf < 2; mf++)
#pragma unroll
        for (int hh = 0; hh < 2; hh++) {
            float gm = gmax[mf * 2 + hh];
            float s = 0.f;
#pragma unroll
            for (int nf = 0; nf < 16; nf++) {
                float e0 = __expf(acc[mf][nf][2 * hh]     - gm);
                float e1 = __expf(acc[mf][nf][2 * hh + 1] - gm);
                acc[mf][nf][2 * hh]     = e0;
                acc[mf][nf][2 * hh + 1] = e1;
                s += e0 + e1;
            }
            s += __shfl_xor_sync(~0u, s, 1);
            s += __shfl_xor_sync(~0u, s, 2);
            if (cq == 0) ssum[(mf * 16 + hh * 8 + r) * 8 + w] = s;
        }
    __syncthreads();
    float ginv[4];
#pragma unroll
    for (int mf = 0; mf < 2; mf++)
#pragma unroll
        for (int hh = 0; hh < 2; hh++) {
            const float* p = ssum + (mf * 16 + hh * 8 + r) * 8;
            float s = 0.f;
#pragma unroll
            for (int j = 0; j < 8; j++) s += p[j];
            ginv[mf * 2 + hh] = 1.f / s;
        }

    // pass 3: attn via streaming stores (write-only output), pbf cached
#pragma unroll
    for (int mf = 0; mf < 2; mf++)
#pragma unroll
        for (int hh = 0; hh < 2; hh++) {
            const int arow = mf * 16 + hh * 8 + r;
            const size_t grow = (size_t)bh * 1024 + i0 + arow;
            const float inv = ginv[mf * 2 + hh];
#pragma unroll
            for (int nf = 0; nf < 16; nf++) {
                int col = w * 128 + nf * 8 + 2 * cq;
                float v0 = acc[mf][nf][2 * hh]     * inv;
                float v1 = acc[mf][nf][2 * hh + 1] * inv;
                stcs2(&attn[grow * 1024 + col], v0, v1);
                pbf[grow * 512 + (col >> 1)] = pack2bf(v0, v1);
            }
        }
}

// ---------------- partial column means ----------------------------------------
__global__ void __launch_bounds__(512) col_mean2(const float* __restrict__ x,
                                                 float* __restrict__ part)
{
    int chunk = blockIdx.x, b = blockIdx.y, d = threadIdx.x;
    const float* p = x + ((size_t)b * LL + chunk * 128) * DM + d;
    float s = 0.f;
#pragma unroll 8
    for (int t = 0; t < 128; t++) s += p[(size_t)t * DM];
    part[(b * 8 + chunk) * DM + d] = s;
}

// ---------------- kernel-size predictor ----------------------------------------
__global__ void __launch_bounds__(256) kernel_pred(const float* __restrict__ part,
                                                   const float* __restrict__ w1,
                                                   const float* __restrict__ b1,
                                                   const float* __restrict__ w2,
                                                   const float* __restrict__ b2,
                                                   const float* __restrict__ tw,
                                                   float* __restrict__ wout,
                                                   int* __restrict__ kout)
{
    int b = blockIdx.x, j = threadIdx.x;
    __shared__ float xs[DM];
    float s0 = 0.f, s1 = 0.f;
#pragma unroll
    for (int c = 0; c < 8; c++) {
        s0 += part[(b * 8 + c) * DM + j];
        s1 += part[(b * 8 + c) * DM + j + 256];
    }
    xs[j]       = s0 * (1.f / 1024.f);
    xs[j + 256] = s1 * (1.f / 1024.f);
    __syncthreads();
    float hj = b1[j];
#pragma unroll 4
    for (int d = 0; d < DM; d++) hj = fmaf(xs[d], w1[d*256 + j], hj);
    hj = fmaxf(hj, 0.f) * w2[j];
    __shared__ float red[256];
    red[j] = hj;
    __syncthreads();
    for (int s = 128; s; s >>= 1) { if (j < s) red[j] += red[j + s]; __syncthreads(); }
    if (j == 0) {
        float sv = 1.f / (1.f + expf(-(red[0] + b2[0])));
        int kk = (int)rintf(sv * 45.f + 5.f);
        kk = max(5, min(kk, MAXK));
        kout[b] = kk;
        float m = -3.4e38f;
        for (int i = 0; i < kk; i++) m = fmaxf(m, tw[i]);
        float e[MAXK], su = 0.f;
        for (int i = 0; i < kk; i++) { e[i] = expf(tw[i] - m); su += e[i]; }
        float inv = 1.f / su;
        for (int i = 0; i < MAXK; i++) wout[b*MAXK + i] = (i < kk) ? e[i] * inv : 0.f;
    }
}

// ---------------- smem-tiled decomp --------------------------------------------
#define DROWS 180
#define DPITCH 132
__global__ void __launch_bounds__(256) decomp_t(const float* __restrict__ x,
                                                const float* __restrict__ w,
                                                const int* __restrict__ kk,
                                                float* __restrict__ out,
                                                unsigned* __restrict__ obf)
{
    extern __shared__ float smf[];
    __shared__ float ws[MAXK];
    const int b = blockIdx.z, t0 = blockIdx.x * 128, d0 = blockIdx.y * 128;
    const int k = kk[b];
    const int tid = threadIdx.x;
    if (tid < MAXK) ws[tid] = w[b * MAXK + tid];
    const int s0 = t0 - (k >> 1);
    const int L  = 127 + k;
    const float* xb = x + (size_t)b * LL * DM;
    const int c4 = tid & 31;
    for (int j = tid >> 5; j < L; j += 8) {
        int src = s0 + j;
        src = src < 0 ? 0 : (src > LL - 1 ? LL - 1 : src);
        *(float4*)&smf[j * DPITCH + c4 * 4] =
            *(const float4*)(xb + (size_t)src * DM + d0 + c4 * 4);
    }
    __syncthreads();
    const int trow = tid >> 5;
    for (int tt = trow; tt < 128; tt += 8) {
        float4 acc = { 0.f, 0.f, 0.f, 0.f };
        for (int i = 0; i < k; i++) {
            float wi = ws[i];
            float4 xv = *(const float4*)&smf[(tt + i) * DPITCH + c4 * 4];
            acc.x = fmaf(wi, xv.x, acc.x); acc.y = fmaf(wi, xv.y, acc.y);
            acc.z = fmaf(wi, xv.z, acc.z); acc.w = fmaf(wi, xv.w, acc.w);
        }
        size_t o = (size_t)(b * LL + t0 + tt) * DM + d0 + c4 * 4;
        float4 xo = *(const float4*)(x + o);
        xo.x -= acc.x; xo.y -= acc.y; xo.z -= acc.z; xo.w -= acc.w;
        *(float4*)(out + o) = xo;
        if (obf) {
            uint2 u = { pack2bf(xo.x, xo.y), pack2bf(xo.z, xo.w) };
            *(uint2*)&obf[(size_t)(b * LL + t0 + tt) * 256 + ((d0 >> 1) + c4 * 2)] = u;
        }
    }
}
#define DSMEM (DROWS * DPITCH * 4)

// -----------------------------------------------------------------------------
static inline int smem_sz(int BM, int BN, bool transB) {
    int astg = BM * 20;
    int bstg = transB ? BN * 20 : 16 * (BN + 8);
    return 4 * (astg + bstg) * 4;
}

extern "C" void kernel_launch(void* const* d_in, const int* in_sizes, int n_in,
                              void* d_out, int out_size)
{
    const float* x       = (const float*)d_in[0];
    const float* Wq      = (const float*)d_in[1];
    const float* bq      = (const float*)d_in[2];
    const float* Wk      = (const float*)d_in[3];
    const float* bk      = (const float*)d_in[4];
    const float* Wv      = (const float*)d_in[5];
    const float* bv      = (const float*)d_in[6];
    const float* Wo      = (const float*)d_in[7];
    const float* bo      = (const float*)d_in[8];
    const float* gate_w  = (const float*)d_in[9];
    const float* gate_b  = (const float*)d_in[10];
    const float* conv1_w = (const float*)d_in[11];
    const float* conv2_w = (const float*)d_in[12];
    const float* tw1     = (const float*)d_in[13];
    const float* kp1_w1  = (const float*)d_in[14];
    const float* kp1_b1  = (const float*)d_in[15];
    const float* kp1_w2  = (const float*)d_in[16];
    const float* kp1_b2  = (const float*)d_in[17];
    const float* tw2     = (const float*)d_in[18];
    const float* kp2_w1  = (const float*)d_in[19];
    const float* kp2_b1  = (const float*)d_in[20];
    const float* kp2_w2  = (const float*)d_in[21];
    const float* kp2_b2  = (const float*)d_in[22];
    const float* attn_sc = (const float*)d_in[23];
    const float* ffn_sc  = (const float*)d_in[24];

    float* res  = (float*)d_out;
    float* attn = (float*)d_out + (size_t)BB*LL*DM;

    unsigned *qkvbf, *pbf, *vp, *t0b, *x2b, *ggb, *hidb, *xb;
    unsigned *wqkvT, *wopT, *wgb, *w1b, *w2b;
    float *bqkv, *x1, *x2, *xg, *wb;
    int* kb;
    cudaGetSymbolAddress((void**)&qkvbf, g_qkvbf);
    cudaGetSymbolAddress((void**)&pbf,   g_pbf);
    cudaGetSymbolAddress((void**)&vp,    g_vp);
    cudaGetSymbolAddress((void**)&t0b,   g_t0b);
    cudaGetSymbolAddress((void**)&x2b,   g_x2b);
    cudaGetSymbolAddress((void**)&ggb,   g_ggb);
    cudaGetSymbolAddress((void**)&hidb,  g_hidb);
    cudaGetSymbolAddress((void**)&xb,    g_xb);
    cudaGetSymbolAddress((void**)&wqkvT, g_wqkvT);
    cudaGetSymbolAddress((void**)&wopT,  g_wopT);
    cudaGetSymbolAddress((void**)&wgb,   g_wgb);
    cudaGetSymbolAddress((void**)&w1b,   g_w1b);
    cudaGetSymbolAddress((void**)&w2b,   g_w2b);
    cudaGetSymbolAddress((void**)&bqkv,  g_bqkv);
    cudaGetSymbolAddress((void**)&x1,    g_x1);
    cudaGetSymbolAddress((void**)&x2,    g_x2);
    cudaGetSymbolAddress((void**)&xg,    g_xg);
    cudaGetSymbolAddress((void**)&wb,    g_w);
    cudaGetSymbolAddress((void**)&kb,    g_kk);

    const int szT  = smem_sz(128, 128, true);
    const int szAV = smem_sz(128,  64, false);

    cudaFuncSetAttribute((const void*)gemm_bf<128,128,0,true ,true >, cudaFuncAttributeMaxDynamicSharedMemorySize, szT);
    cudaFuncSetAttribute((const void*)gemm_bf<128, 64,5,false,true >, cudaFuncAttributeMaxDynamicSharedMemorySize, szAV);
    cudaFuncSetAttribute((const void*)gemm_bf<128,128,1,true ,false>, cudaFuncAttributeMaxDynamicSharedMemorySize, szT);
    cudaFuncSetAttribute((const void*)gemm_bf<128,128,2,true ,true >, cudaFuncAttributeMaxDynamicSharedMemorySize, szT);
    cudaFuncSetAttribute((const void*)gemm_bf<128,128,3,true ,true >, cudaFuncAttributeMaxDynamicSharedMemorySize, szT);
    cudaFuncSetAttribute((const void*)gemm_bf<128,128,4,true ,false>, cudaFuncAttributeMaxDynamicSharedMemorySize, szT);
    cudaFuncSetAttribute((const void*)scores_sm, cudaFuncAttributeMaxDynamicSharedMemorySize, SCSM);
    cudaFuncSetAttribute((const void*)decomp_t, cudaFuncAttributeMaxDynamicSharedMemorySize, DSMEM);

    const dim3 blk(256);

    pack_all<<<7430, 256>>>(x, Wq, Wk, Wv, Wo, gate_w, conv1_w, conv2_w,
                            bq, bk, bv, xb, wqkvT, wopT, wgb, w1b, w2b, bqkv);

    gemm_bf<128,128,0,true,true><<<dim3(QKVN/128, BLN/128, 1), blk, szT>>>(
        xb, wqkvT, bqkv, nullptr, nullptr, 1.f, qkvbf,
        DM, 256, 256, QKVN, 0,0,0,0,0,0);

    vpack<<<(8*512*512)/256, 256>>>((const __nv_bfloat16*)qkvbf, vp);

    scores_sm<<<dim3(LL/32, BB*HH), blk, SCSM>>>(qkvbf, attn, pbf);

    gemm_bf<128,64,5,false,true><<<dim3(1, LL/128, BB*HH), blk, szAV>>>(
        pbf, vp, nullptr, nullptr, nullptr, 1.f, t0b,
        LL, 512, 512, DM,
        (long)8*LL*512, (long)LL*512, 262144, 64, (long)LL*DM, 64);

    gemm_bf<128,128,1,true,false><<<dim3(DM/128, BLN/128, 1), blk, szT>>>(
        t0b, wopT, bo, x, attn_sc, 1.f, x1,
        DM, 256, 256, DM, 0,0,0,0,0,0);

    col_mean2<<<dim3(8, BB), 512>>>(x1, xg);
    kernel_pred<<<BB, 256>>>(xg, kp1_w1, kp1_b1, kp1_w2, kp1_b2, tw1, wb, kb);
    decomp_t<<<dim3(8, 4, BB), 256, DSMEM>>>(x1, wb, kb, x2, x2b);

    gemm_bf<128,128,2,true,true><<<dim3(DM/128, BLN/128, 1), blk, szT>>>(
        x2b, wgb, gate_b, x2, nullptr, 1.f, ggb,
        DM, 256, 256, DM, 0,0,0,0,0,0);
    gemm_bf<128,128,3,true,true><<<dim3(DFF/128, BLN/128, 1), blk, szT>>>(
        ggb, w1b, nullptr, nullptr, nullptr, 1.f, hidb,
        DM, 256, 256, DFF, 0,0,0,0,0,0);
    gemm_bf<128,128,4,true,false><<<dim3(DM/128, BLN/128, 1), blk, szT>>>(
        hidb, w2b, nullptr, x2, ffn_sc, 1.f, x1,
        DFF, 1024, 1024, DM, 0,0,0,0,0,0);

    col_mean2<<<dim3(8, BB), 512>>>(x1, xg);
    kernel_pred<<<BB, 256>>>(xg, kp2_w1, kp2_b1, kp2_w2, kp2_b2, tw2, wb, kb);
    decomp_t<<<dim3(8, 4, BB), 256, DSMEM>>>(x1, wb, kb, res, nullptr);
}

// round 16
// speedup vs baseline: 1.0330x; 1.0237x over previous
#include <cuda_runtime.h>
#include <cuda_bf16.h>
#include <math.h>
#include <stdint.h>

#define BB 8
#define LL 1024
#define DM 512
#define HH 8
#define HD 64
#define DFF 2048
#define BLN (BB*LL)
#define MAXK 50
#define QKVN 1536

// ---------------- scratch (device globals; no allocations allowed) ----------
__device__ __align__(16) unsigned g_qkvbf[(size_t)BLN*768];
__device__ __align__(16) unsigned g_pbf[(size_t)64*1024*512];
__device__ __align__(16) unsigned g_vp[(size_t)8*512*512];
__device__ __align__(16) unsigned g_t0b[BLN*256];
__device__ __align__(16) unsigned g_x2b[BLN*256];
__device__ __align__(16) unsigned g_ggb[BLN*256];
__device__ __align__(16) unsigned g_hidb[(size_t)BLN*1024];
__device__ __align__(16) unsigned g_xb[BLN*256];
__device__ __align__(16) unsigned g_wqkvT[QKVN*256];
__device__ __align__(16) unsigned g_wopT[512*256];
__device__ __align__(16) unsigned g_wgb[512*256];
__device__ __align__(16) unsigned g_w1b[2048*256];
__device__ __align__(16) unsigned g_w2b[512*1024];
__device__ float g_bqkv[QKVN];
__device__ float g_x1[BLN*DM];
__device__ float g_x2[BLN*DM];
__device__ float g_xg[BB*8*DM];
__device__ float g_w [BB*MAXK];
__device__ int   g_kk[BB];

// ---------------- helpers ----------------------------------------------------
__device__ __forceinline__ unsigned pack2bf(float a, float b) {
    __nv_bfloat162 w;
    w.x = __float2bfloat16_rn(a);
    w.y = __float2bfloat16_rn(b);
    return *(unsigned*)&w;
}

__device__ __forceinline__ void mma_bf16(float c[4], const unsigned a[4], const unsigned b[2]) {
    asm volatile(
        "mma.sync.aligned.m16n8k16.row.col.f32.bf16.bf16.f32 "
        "{%0,%1,%2,%3},{%4,%5,%6,%7},{%8,%9},{%0,%1,%2,%3};"
        : "+f"(c[0]), "+f"(c[1]), "+f"(c[2]), "+f"(c[3])
        : "r"(a[0]), "r"(a[1]), "r"(a[2]), "r"(a[3]), "r"(b[0]), "r"(b[1]));
}

__device__ __forceinline__ void ldsm_x4(unsigned r[4], uint32_t addr) {
    asm volatile("ldmatrix.sync.aligned.m8n8.x4.shared.b16 {%0,%1,%2,%3}, [%4];"
        : "=r"(r[0]), "=r"(r[1]), "=r"(r[2]), "=r"(r[3]) : "r"(addr));
}
__device__ __forceinline__ void ldsm_x2(unsigned r[2], uint32_t addr) {
    asm volatile("ldmatrix.sync.aligned.m8n8.x2.shared.b16 {%0,%1}, [%2];"
        : "=r"(r[0]), "=r"(r[1]) : "r"(addr));
}

__device__ __forceinline__ void cpa16(void* dst, const void* src) {
    unsigned d = (unsigned)__cvta_generic_to_shared(dst);
    asm volatile("cp.async.cg.shared.global [%0], [%1], 16;" :: "r"(d), "l"(src));
}
__device__ __forceinline__ void cpa_commit() { asm volatile("cp.async.commit_group;"); }
template<int N>
__device__ __forceinline__ void cpa_wait() { asm volatile("cp.async.wait_group %0;" :: "n"(N)); }
__device__ __forceinline__ uint32_t s2u(const void* p) {
    return (uint32_t)__cvta_generic_to_shared(p);
}

// ---------------- pack kernels (round-12 structure) ----------------------------
__global__ void __launch_bounds__(256) cvt_bf(const float4* __restrict__ src,
                                              uint2* __restrict__ dst, int n4)
{
    int i = blockIdx.x * 256 + threadIdx.x;
    if (i < n4) {
        float4 v = src[i];
        uint2 u = { pack2bf(v.x, v.y), pack2bf(v.z, v.w) };
        dst[i] = u;
    }
}

__device__ __forceinline__ void tpose_blk(const float* __restrict__ W,
                                          __nv_bfloat16* __restrict__ out,
                                          int rowOff, int idx)
{
    __shared__ float t[32][33];
    int k0 = (idx & 15) * 32, n0 = (idx >> 4) * 32;
    int tx = threadIdx.x & 31, ty = threadIdx.x >> 5;
#pragma unroll
    for (int i = 0; i < 4; i++)
        t[ty + 8 * i][tx] = W[(size_t)(k0 + ty + 8 * i) * 512 + n0 + tx];
    __syncthreads();
#pragma unroll
    for (int i = 0; i < 4; i++)
        out[(size_t)(rowOff + n0 + ty + 8 * i) * 512 + k0 + tx] =
            __float2bfloat16_rn(t[tx][ty + 8 * i]);
}
__device__ __forceinline__ void cvt_blk(const float4* __restrict__ src,
                                        uint2* __restrict__ dst, int idx, int n4)
{
    int i = idx * 256 + threadIdx.x;
    if (i < n4) {
        float4 v = src[i];
        uint2 u = { pack2bf(v.x, v.y), pack2bf(v.z, v.w) };
        dst[i] = u;
    }
}

__global__ void __launch_bounds__(256) pack_weights(
    const float* __restrict__ Wq, const float* __restrict__ Wk,
    const float* __restrict__ Wv, const float* __restrict__ Wo,
    const float* __restrict__ gate_w, const float* __restrict__ conv1_w,
    const float* __restrict__ conv2_w,
    const float* __restrict__ bq, const float* __restrict__ bk,
    const float* __restrict__ bv,
    unsigned* __restrict__ wqkvT, unsigned* __restrict__ wopT,
    unsigned* __restrict__ wgb, unsigned* __restrict__ w1b,
    unsigned* __restrict__ w2b, float* __restrict__ bqkv)
{
    int bid = blockIdx.x;
    if (bid < 256) {
        tpose_blk(Wq, (__nv_bfloat16*)wqkvT, 0, bid);
    } else if (bid < 512) {
        tpose_blk(Wk, (__nv_bfloat16*)wqkvT, 512, bid - 256);
    } else if (bid < 768) {
        tpose_blk(Wv, (__nv_bfloat16*)wqkvT, 1024, bid - 512);
    } else if (bid < 1024) {
        tpose_blk(Wo, (__nv_bfloat16*)wopT, 0, bid - 768);
    } else if (bid < 1280) {
        cvt_blk((const float4*)gate_w, (uint2*)wgb, bid - 1024, DM*DM/4);
    } else if (bid < 2304) {
        cvt_blk((const float4*)conv1_w, (uint2*)w1b, bid - 1280, DM*DFF/4);
    } else if (bid < 3328) {
        cvt_blk((const float4*)conv2_w, (uint2*)w2b, bid - 2304, DM*DFF/4);
    } else {
        int i = (bid - 3328) * 256 + threadIdx.x;
        if (i < QKVN)
            bqkv[i] = i < 512 ? bq[i] : (i < 1024 ? bk[i - 512] : bv[i - 1024]);
    }
}

__global__ void __launch_bounds__(256) vpack(const __nv_bfloat16* __restrict__ qkv,
                                             unsigned* __restrict__ vp)
{
    int i = blockIdx.x * 256 + threadIdx.x;
    int c = i & 511, jr = (i >> 9) & 511, b = i >> 18;
    const __nv_bfloat16* v0 = qkv + ((size_t)(b * 1024 + 2 * jr)) * QKVN + 1024 + c;
    __nv_bfloat162 w;
    w.x = v0[0];
    w.y = v0[QKVN];
    vp[i] = *(unsigned*)&w;
}

// ---------------- bf16 tensor-core GEMM (round-12 pipeline) -------------------
template<int BM, int BN, int EPI, bool TRANSB, bool OUTBF>
__global__ void __launch_bounds__(256, 2) gemm_bf(
    const unsigned* __restrict__ A, const unsigned* __restrict__ B,
    const float* __restrict__ bias, const float* __restrict__ aux,
    const float* __restrict__ scale, float alpha, void* __restrict__ Cv,
    int K, int ldaw, int ldbw, int ldc,
    long sAhi, long sAlo, long sBhi, long sBlo, long sChi, long sClo)
{
    constexpr int SK   = 20;
    constexpr int SBnt = BN + 8;
    constexpr int ASTG = BM * SK;
    constexpr int BSTG = TRANSB ? BN * SK : 16 * SBnt;
    constexpr int NF   = BN / 32;
    constexpr int NA   = BM * 4 / 256;
    constexpr int NBt  = BN * 4 / 256 ? BN * 4 / 256 : 1;
    constexpr int NBn  = 16 * (BN / 4) / 256 ? 16 * (BN / 4) / 256 : 1;

    extern __shared__ unsigned smem[];
    unsigned* As = smem;
    unsigned* Bs = smem + 4 * ASTG;

    const int z = blockIdx.z;
    const unsigned* Ab = A + (size_t)(z >> 3) * sAhi + (size_t)(z & 7) * sAlo
                           + (size_t)blockIdx.y * BM * ldaw;
    const unsigned* Bb = B + (size_t)(z >> 3) * sBhi + (size_t)(z & 7) * sBlo;
    if (TRANSB) Bb += (size_t)blockIdx.x * BN * ldbw;
    else        Bb += (size_t)blockIdx.x * BN;

    const int t = threadIdx.x;
    const int lane = t & 31, w = t >> 5;
    const int wr = w >> 2, wc = w & 3;
    const int r = lane >> 2, cq = lane & 3;
    const int mB = wr * 64, nB = wc * (BN / 4);

    const uint32_t smem_u = s2u(smem);
    const uint32_t laneA4 = (((lane & 15) * SK) + ((lane >> 4) << 2)) << 2;
    const uint32_t laneB4 = (((lane & 7) * SK) + (((lane >> 3) & 1) << 2)) << 2;

    const int NC = K >> 5;

    auto issue = [&](int s) {
        if (s < NC) {
            const int k0w = s << 4;
            unsigned* Ad = As + (s & 3) * ASTG;
#pragma unroll
            for (int i = 0; i < NA; i++) {
                int cid = t + i * 256;
                int row = cid >> 2, jw = (cid & 3) * 4;
                cpa16(Ad + row * SK + jw, Ab + (size_t)row * ldaw + k0w + jw);
            }
            unsigned* Bd = Bs + (s & 3) * BSTG;
            if (TRANSB) {
#pragma unroll
                for (int i = 0; i < NBt; i++) {
                    int cid = t + i * 256;
                    int row = cid >> 2, jw = (cid & 3) * 4;
                    cpa16(Bd + row * SK + jw, Bb + (size_t)row * ldbw + k0w + jw);
                }
            } else {
#pragma unroll
                for (int i = 0; i < NBn; i++) {
                    int cid = t + i * 256;
                    int kr = cid / (BN / 4), n4 = (cid % (BN / 4)) * 4;
                    cpa16(Bd + kr * SBnt + n4, Bb + (size_t)(k0w + kr) * ldbw + n4);
                }
            }
        }
        cpa_commit();
    };

    float acc[4][NF][4];
#pragma unroll
    for (int i = 0; i < 4; i++)
#pragma unroll
        for (int j = 0; j < NF; j++)
#pragma unroll
            for (int e = 0; e < 4; e++) acc[i][j][e] = 0.f;

    issue(0); issue(1); issue(2);

    for (int c = 0; c < NC; c++) {
        cpa_wait<2>();
        __syncthreads();
        const unsigned* Bc = Bs + (c & 3) * BSTG;
#pragma unroll
        for (int ks = 0; ks < 2; ks++) {
            const int kw = ks * 8;
            unsigned af[4][4], bf[NF][2];
            uint32_t abase = smem_u + (((c & 3) * ASTG + mB * SK + kw) << 2) + laneA4;
#pragma unroll
            for (int mf = 0; mf < 4; mf++)
                ldsm_x4(af[mf], abase + ((mf * 16 * SK) << 2));
            if (TRANSB) {
                uint32_t bbase = smem_u +
                    ((4 * ASTG + (c & 3) * BSTG + nB * SK + kw) << 2) + laneB4;
#pragma unroll
                for (int nf = 0; nf < NF; nf++)
                    ldsm_x2(bf[nf], bbase + ((nf * 8 * SK) << 2));
            } else {
#pragma unroll
                for (int nf = 0; nf < NF; nf++) {
                    const unsigned* bp = Bc + (kw + cq) * SBnt + nB + nf * 8 + r;
                    bf[nf][0] = bp[0];
                    bf[nf][1] = bp[4 * SBnt];
                }
            }
#pragma unroll
            for (int mf = 0; mf < 4; mf++)
#pragma unroll
                for (int nf = 0; nf < NF; nf++)
                    mma_bf16(acc[mf][nf], af[mf], bf[nf]);
        }
        issue(c + 3);
    }

    float scv = 1.f;
    if constexpr (EPI == 1 || EPI == 4) scv = *scale;
    float* Cf = (float*)Cv;
    unsigned* Cw = (unsigned*)Cv;
    const size_t cOff = (size_t)(z >> 3) * sChi + (size_t)(z & 7) * sClo;
    const int rowBase = blockIdx.y * BM + mB;
    const int colBase = blockIdx.x * BN + nB;
#pragma unroll
    for (int mf = 0; mf < 4; mf++) {
#pragma unroll
        for (int nf = 0; nf < NF; nf++) {
            int n = colBase + nf * 8 + 2 * cq;
#pragma unroll
            for (int h = 0; h < 2; h++) {
                int m = rowBase + mf * 16 + r + 8 * h;
                size_t idx = (size_t)m * ldc + n;
                float v0 = acc[mf][nf][2 * h + 0] * alpha;
                float v1 = acc[mf][nf][2 * h + 1] * alpha;
                if constexpr (EPI == 0) { v0 += bias[n]; v1 += bias[n + 1]; }
                else if constexpr (EPI == 1) {
                    v0 = aux[idx]     + scv * (v0 + bias[n]);
                    v1 = aux[idx + 1] + scv * (v1 + bias[n + 1]);
                } else if constexpr (EPI == 2) {
                    v0 = aux[idx]     / (1.f + expf(-(v0 + bias[n])));
                    v1 = aux[idx + 1] / (1.f + expf(-(v1 + bias[n + 1])));
                } else if constexpr (EPI == 3) {
                    v0 = fmaxf(v0, 0.f); v1 = fmaxf(v1, 0.f);
                } else if constexpr (EPI == 4) {
                    v0 = aux[idx]     + scv * v0;
                    v1 = aux[idx + 1] + scv * v1;
                }
                if constexpr (OUTBF) {
                    Cw[(cOff + idx) >> 1] = pack2bf(v0, v1);
                } else {
                    float2 o = { v0, v1 };
                    *(float2*)&Cf[cOff + idx] = o;
                }
            }
        }
    }
}

// ---------------- fused scores + softmax (per-warp K slices) ------------------
// Warp w owns score columns [w*128, w*128+128) == K rows [w*128, ...).
// Each warp cp.asyncs ONLY its K slice + a private Q copy, waits on its own
// group, and starts MMA immediately — no CTA-wide load barrier.
#define SK2 36
#define KWORDS (1024 * SK2)
#define QOFF   KWORDS                 // 8 Q copies follow K
#define SCSM   ((1024 + 8 * 32) * SK2 * 4 + 32 * 8 * 4 * 2)

__global__ void __launch_bounds__(256, 1) scores_sm(
    const unsigned* __restrict__ qkv, float* __restrict__ attn,
    unsigned* __restrict__ pbf)
{
    extern __shared__ unsigned sm[];
    unsigned* Ks = sm;                            // [1024][SK2]
    unsigned* Q8 = sm + QOFF;                     // [8][32][SK2]
    float* smax  = (float*)(sm + QOFF + 8 * 32 * SK2);   // [32][8]
    float* ssum  = smax + 32 * 8;

    const int bh = blockIdx.y, b = bh >> 3, h = bh & 7;
    const int i0 = blockIdx.x * 32;
    const int tid = threadIdx.x;
    const int lane = tid & 31, w = tid >> 5;

    const unsigned* qbase = qkv + (size_t)(b * 1024 + i0) * 768 + h * 32;
    const unsigned* kbase = qkv + (size_t)b * 1024 * 768 + 256 + h * 32;

    // per-warp loads: own Q copy (256 chunks) + own K slice (1024 chunks)
    unsigned* Qw = Q8 + w * 32 * SK2;
#pragma unroll
    for (int i = 0; i < 8; i++) {
        int cid = lane + i * 32;
        int row = cid >> 3, jw = (cid & 7) * 4;
        cpa16(Qw + row * SK2 + jw, qbase + (size_t)row * 768 + jw);
    }
    const int kr0 = w * 128;
#pragma unroll
    for (int i = 0; i < 32; i++) {
        int cid = lane + i * 32;
        int rowl = cid >> 3, jw = (cid & 7) * 4;
        cpa16(Ks + (kr0 + rowl) * SK2 + jw, kbase + (size_t)(kr0 + rowl) * 768 + jw);
    }
    cpa_commit();
    cpa_wait<0>();
    __syncwarp();

    const int r = lane >> 2, cq = lane & 3;
    const uint32_t smem_u = s2u(sm);
    const uint32_t laneA4 = (((lane & 15) * SK2) + ((lane >> 4) << 2)) << 2;
    const uint32_t laneB4 = (((lane & 7) * SK2) + (((lane >> 3) & 1) << 2)) << 2;

    float acc[2][16][4];
#pragma unroll
    for (int mf = 0; mf < 2; mf++)
#pragma unroll
        for (int nf = 0; nf < 16; nf++)
#pragma unroll
            for (int e = 0; e < 4; e++) acc[mf][nf][e] = 0.f;

#pragma unroll
    for (int kc = 0; kc < 4; kc++) {
        const int kw = kc * 8;
        unsigned af[2][4];
        uint32_t ab = smem_u + (((QOFF + w * 32 * SK2) + kw) << 2) + laneA4;
        ldsm_x4(af[0], ab);
        ldsm_x4(af[1], ab + ((16 * SK2) << 2));
#pragma unroll
        for (int nf = 0; nf < 16; nf++) {
            unsigned bf[2];
            uint32_t bb = smem_u + (((kr0 + nf * 8) * SK2 + kw) << 2) + laneB4;
            ldsm_x2(bf, bb);
            mma_bf16(acc[0][nf], af[0], bf);
            mma_bf16(acc[1][nf], af[1], bf);
        }
    }

#pragma unroll
    for (int mf = 0; mf < 2; mf++)
#pragma unroll
        for (int nf = 0; nf < 16; nf++)
#pragma unroll
            for (int e = 0; e < 4; e++) acc[mf][nf][e] *= 0.125f;

    // cross-warp softmax (CTA barrier required here anyway)
#pragma unroll
    for (int mf = 0; mf < 2; mf++)
#pragma unroll
        for (int hh = 0; hh < 2; hh++) {
            float m = -3.4e38f;
#pragma unroll
            for (int nf = 0; nf < 16; nf++)
                m = fmaxf(m, fmaxf(acc[mf][nf][2 * hh], acc[mf][nf][2 * hh + 1]));
            m = fmaxf(m, __shfl_xor_sync(~0u, m, 1));
            m = fmaxf(m, __shfl_xor_sync(~0u, m, 2));
            if (cq == 0) smax[(mf * 16 + hh * 8 + r) * 8 + w] = m;
        }
    __syncthreads();
    float gmax[4];
#pragma unroll
    for (int mf = 0; mf < 2; mf++)
#pragma unroll
        for (int hh = 0; hh < 2; hh++) {
            const float* p = smax + (mf * 16 + hh * 8 + r) * 8;
            float m = p[0];
#pragma unroll
            for (int j = 1; j < 8; j++) m = fmaxf(m, p[j]);
            gmax[mf * 2 + hh] = m;
        }

#pragma unroll
    for (int mf = 0; mf < 2; mf++)
#pragma unroll
        for (int hh = 0; hh < 2; hh++) {
            float gm = gmax[mf * 2 + hh];
            float s = 0.f;
#pragma unroll
            for (int nf = 0; nf < 16; nf++) {
                float e0 = __expf(acc[mf][nf][2 * hh]     - gm);
                float e1 = __expf(acc[mf][nf][2 * hh + 1] - gm);
                acc[mf][nf][2 * hh]     = e0;
                acc[mf][nf][2 * hh + 1] = e1;
                s += e0 + e1;
            }
            s += __shfl_xor_sync(~0u, s, 1);
            s += __shfl_xor_sync(~0u, s, 2);
            if (cq == 0) ssum[(mf * 16 + hh * 8 + r) * 8 + w] = s;
        }
    __syncthreads();
    float ginv[4];
#pragma unroll
    for (int mf = 0; mf < 2; mf++)
#pragma unroll
        for (int hh = 0; hh < 2; hh++) {
            const float* p = ssum + (mf * 16 + hh * 8 + r) * 8;
            float s = 0.f;
#pragma unroll
            for (int j = 0; j < 8; j++) s += p[j];
            ginv[mf * 2 + hh] = 1.f / s;
        }

#pragma unroll
    for (int mf = 0; mf < 2; mf++)
#pragma unroll
        for (int hh = 0; hh < 2; hh++) {
            const int arow = mf * 16 + hh * 8 + r;
            const size_t grow = (size_t)bh * 1024 + i0 + arow;
            const float inv = ginv[mf * 2 + hh];
#pragma unroll
            for (int nf = 0; nf < 16; nf++) {
                int col = w * 128 + nf * 8 + 2 * cq;
                float v0 = acc[mf][nf][2 * hh]     * inv;
                float v1 = acc[mf][nf][2 * hh + 1] * inv;
                float2 o = { v0, v1 };
                *(float2*)&attn[grow * 1024 + col] = o;
                pbf[grow * 512 + (col >> 1)] = pack2bf(v0, v1);
            }
        }
}

// ---------------- partial column means ----------------------------------------
__global__ void __launch_bounds__(512) col_mean2(const float* __restrict__ x,
                                                 float* __restrict__ part)
{
    int chunk = blockIdx.x, b = blockIdx.y, d = threadIdx.x;
    const float* p = x + ((size_t)b * LL + chunk * 128) * DM + d;
    float s = 0.f;
#pragma unroll 8
    for (int t = 0; t < 128; t++) s += p[(size_t)t * DM];
    part[(b * 8 + chunk) * DM + d] = s;
}

// ---------------- kernel-size predictor ----------------------------------------
__global__ void __launch_bounds__(256) kernel_pred(const float* __restrict__ part,
                                                   const float* __restrict__ w1,
                                                   const float* __restrict__ b1,
                                                   const float* __restrict__ w2,
                                                   const float* __restrict__ b2,
                                                   const float* __restrict__ tw,
                                                   float* __restrict__ wout,
                                                   int* __restrict__ kout)
{
    int b = blockIdx.x, j = threadIdx.x;
    __shared__ float xs[DM];
    float s0 = 0.f, s1 = 0.f;
#pragma unroll
    for (int c = 0; c < 8; c++) {
        s0 += part[(b * 8 + c) * DM + j];
        s1 += part[(b * 8 + c) * DM + j + 256];
    }
    xs[j]       = s0 * (1.f / 1024.f);
    xs[j + 256] = s1 * (1.f / 1024.f);
    __syncthreads();
    float hj = b1[j];
#pragma unroll 4
    for (int d = 0; d < DM; d++) hj = fmaf(xs[d], w1[d*256 + j], hj);
    hj = fmaxf(hj, 0.f) * w2[j];
    __shared__ float red[256];
    red[j] = hj;
    __syncthreads();
    for (int s = 128; s; s >>= 1) { if (j < s) red[j] += red[j + s]; __syncthreads(); }
    if (j == 0) {
        float sv = 1.f / (1.f + expf(-(red[0] + b2[0])));
        int kk = (int)rintf(sv * 45.f + 5.f);
        kk = max(5, min(kk, MAXK));
        kout[b] = kk;
        float m = -3.4e38f;
        for (int i = 0; i < kk; i++) m = fmaxf(m, tw[i]);
        float e[MAXK], su = 0.f;
        for (int i = 0; i < kk; i++) { e[i] = expf(tw[i] - m); su += e[i]; }
        float inv = 1.f / su;
        for (int i = 0; i < MAXK; i++) wout[b*MAXK + i] = (i < kk) ? e[i] * inv : 0.f;
    }
}

// ---------------- smem-tiled decomp --------------------------------------------
#define DROWS 180
#define DPITCH 132
__global__ void __launch_bounds__(256) decomp_t(const float* __restrict__ x,
                                                const float* __restrict__ w,
                                                const int* __restrict__ kk,
                                                float* __restrict__ out,
                                                unsigned* __restrict__ obf)
{
    extern __shared__ float smf[];
    __shared__ float ws[MAXK];
    const int b = blockIdx.z, t0 = blockIdx.x * 128, d0 = blockIdx.y * 128;
    const int k = kk[b];
    const int tid = threadIdx.x;
    if (tid < MAXK) ws[tid] = w[b * MAXK + tid];
    const int s0 = t0 - (k >> 1);
    const int L  = 127 + k;
    const float* xb = x + (size_t)b * LL * DM;
    const int c4 = tid & 31;
    for (int j = tid >> 5; j < L; j += 8) {
        int src = s0 + j;
        src = src < 0 ? 0 : (src > LL - 1 ? LL - 1 : src);
        *(float4*)&smf[j * DPITCH + c4 * 4] =
            *(const float4*)(xb + (size_t)src * DM + d0 + c4 * 4);
    }
    __syncthreads();
    const int trow = tid >> 5;
    for (int tt = trow; tt < 128; tt += 8) {
        float4 acc = { 0.f, 0.f, 0.f, 0.f };
        for (int i = 0; i < k; i++) {
            float wi = ws[i];
            float4 xv = *(const float4*)&smf[(tt + i) * DPITCH + c4 * 4];
            acc.x = fmaf(wi, xv.x, acc.x); acc.y = fmaf(wi, xv.y, acc.y);
            acc.z = fmaf(wi, xv.z, acc.z); acc.w = fmaf(wi, xv.w, acc.w);
        }
        size_t o = (size_t)(b * LL + t0 + tt) * DM + d0 + c4 * 4;
        float4 xo = *(const float4*)(x + o);
        xo.x -= acc.x; xo.y -= acc.y; xo.z -= acc.z; xo.w -= acc.w;
        *(float4*)(out + o) = xo;
        if (obf) {
            uint2 u = { pack2bf(xo.x, xo.y), pack2bf(xo.z, xo.w) };
            *(uint2*)&obf[(size_t)(b * LL + t0 + tt) * 256 + ((d0 >> 1) + c4 * 2)] = u;
        }
    }
}
#define DSMEM (DROWS * DPITCH * 4)

// -----------------------------------------------------------------------------
static inline int smem_sz(int BM, int BN, bool transB) {
    int astg = BM * 20;
    int bstg = transB ? BN * 20 : 16 * (BN + 8);
    return 4 * (astg + bstg) * 4;
}

extern "C" void kernel_launch(void* const* d_in, const int* in_sizes, int n_in,
                              void* d_out, int out_size)
{
    const float* x       = (const float*)d_in[0];
    const float* Wq      = (const float*)d_in[1];
    const float* bq      = (const float*)d_in[2];
    const float* Wk      = (const float*)d_in[3];
    const float* bk      = (const float*)d_in[4];
    const float* Wv      = (const float*)d_in[5];
    const float* bv      = (const float*)d_in[6];
    const float* Wo      = (const float*)d_in[7];
    const float* bo      = (const float*)d_in[8];
    const float* gate_w  = (const float*)d_in[9];
    const float* gate_b  = (const float*)d_in[10];
    const float* conv1_w = (const float*)d_in[11];
    const float* conv2_w = (const float*)d_in[12];
    const float* tw1     = (const float*)d_in[13];
    const float* kp1_w1  = (const float*)d_in[14];
    const float* kp1_b1  = (const float*)d_in[15];
    const float* kp1_w2  = (const float*)d_in[16];
    const float* kp1_b2  = (const float*)d_in[17];
    const float* tw2     = (const float*)d_in[18];
    const float* kp2_w1  = (const float*)d_in[19];
    const float* kp2_b1  = (const float*)d_in[20];
    const float* kp2_w2  = (const float*)d_in[21];
    const float* kp2_b2  = (const float*)d_in[22];
    const float* attn_sc = (const float*)d_in[23];
    const float* ffn_sc  = (const float*)d_in[24];

    float* res  = (float*)d_out;
    float* attn = (float*)d_out + (size_t)BB*LL*DM;

    unsigned *qkvbf, *pbf, *vp, *t0b, *x2b, *ggb, *hidb, *xb;
    unsigned *wqkvT, *wopT, *wgb, *w1b, *w2b;
    float *bqkv, *x1, *x2, *xg, *wb;
    int* kb;
    cudaGetSymbolAddress((void**)&qkvbf, g_qkvbf);
    cudaGetSymbolAddress((void**)&pbf,   g_pbf);
    cudaGetSymbolAddress((void**)&vp,    g_vp);
    cudaGetSymbolAddress((void**)&t0b,   g_t0b);
    cudaGetSymbolAddress((void**)&x2b,   g_x2b);
    cudaGetSymbolAddress((void**)&ggb,   g_ggb);
    cudaGetSymbolAddress((void**)&hidb,  g_hidb);
    cudaGetSymbolAddress((void**)&xb,    g_xb);
    cudaGetSymbolAddress((void**)&wqkvT, g_wqkvT);
    cudaGetSymbolAddress((void**)&wopT,  g_wopT);
    cudaGetSymbolAddress((void**)&wgb,   g_wgb);
    cudaGetSymbolAddress((void**)&w1b,   g_w1b);
    cudaGetSymbolAddress((void**)&w2b,   g_w2b);
    cudaGetSymbolAddress((void**)&bqkv,  g_bqkv);
    cudaGetSymbolAddress((void**)&x1,    g_x1);
    cudaGetSymbolAddress((void**)&x2,    g_x2);
    cudaGetSymbolAddress((void**)&xg,    g_xg);
    cudaGetSymbolAddress((void**)&wb,    g_w);
    cudaGetSymbolAddress((void**)&kb,    g_kk);

    const int szT  = smem_sz(128, 128, true);
    const int szAV = smem_sz(128,  64, false);

    cudaFuncSetAttribute((const void*)gemm_bf<128,128,0,true ,true >, cudaFuncAttributeMaxDynamicSharedMemorySize, szT);
    cudaFuncSetAttribute((const void*)gemm_bf<128, 64,5,false,true >, cudaFuncAttributeMaxDynamicSharedMemorySize, szAV);
    cudaFuncSetAttribute((const void*)gemm_bf<128,128,1,true ,false>, cudaFuncAttributeMaxDynamicSharedMemorySize, szT);
    cudaFuncSetAttribute((const void*)gemm_bf<128,128,2,true ,true >, cudaFuncAttributeMaxDynamicSharedMemorySize, szT);
    cudaFuncSetAttribute((const void*)gemm_bf<128,128,3,true ,true >, cudaFuncAttributeMaxDynamicSharedMemorySize, szT);
    cudaFuncSetAttribute((const void*)gemm_bf<128,128,4,true ,false>, cudaFuncAttributeMaxDynamicSharedMemorySize, szT);
    cudaFuncSetAttribute((const void*)scores_sm, cudaFuncAttributeMaxDynamicSharedMemorySize, SCSM);
    cudaFuncSetAttribute((const void*)decomp_t, cudaFuncAttributeMaxDynamicSharedMemorySize, DSMEM);

    const dim3 blk(256);

    // ---- pack / convert (round-12 structure: two launches) ----
    cvt_bf<<<(BLN*DM/4 + 255)/256, 256>>>((const float4*)x, (uint2*)xb, BLN*DM/4);
    pack_weights<<<3334, 256>>>(Wq, Wk, Wv, Wo, gate_w, conv1_w, conv2_w,
                                bq, bk, bv, wqkvT, wopT, wgb, w1b, w2b, bqkv);

    gemm_bf<128,128,0,true,true><<<dim3(QKVN/128, BLN/128, 1), blk, szT>>>(
        xb, wqkvT, bqkv, nullptr, nullptr, 1.f, qkvbf,
        DM, 256, 256, QKVN, 0,0,0,0,0,0);

    vpack<<<(8*512*512)/256, 256>>>((const __nv_bfloat16*)qkvbf, vp);

    scores_sm<<<dim3(LL/32, BB*HH), blk, SCSM>>>(qkvbf, attn, pbf);

    gemm_bf<128,64,5,false,true><<<dim3(1, LL/128, BB*HH), blk, szAV>>>(
        pbf, vp, nullptr, nullptr, nullptr, 1.f, t0b,
        LL, 512, 512, DM,
        (long)8*LL*512, (long)LL*512, 262144, 64, (long)LL*DM, 64);

    gemm_bf<128,128,1,true,false><<<dim3(DM/128, BLN/128, 1), blk, szT>>>(
        t0b, wopT, bo, x, attn_sc, 1.f, x1,
        DM, 256, 256, DM, 0,0,0,0,0,0);

    col_mean2<<<dim3(8, BB), 512>>>(x1, xg);
    kernel_pred<<<BB, 256>>>(xg, kp1_w1, kp1_b1, kp1_w2, kp1_b2, tw1, wb, kb);
    decomp_t<<<dim3(8, 4, BB), 256, DSMEM>>>(x1, wb, kb, x2, x2b);

    gemm_bf<128,128,2,true,true><<<dim3(DM/128, BLN/128, 1), blk, szT>>>(
        x2b, wgb, gate_b, x2, nullptr, 1.f, ggb,
        DM, 256, 256, DM, 0,0,0,0,0,0);
    gemm_bf<128,128,3,true,true><<<dim3(DFF/128, BLN/128, 1), blk, szT>>>(
        ggb, w1b, nullptr, nullptr, nullptr, 1.f, hidb,
        DM, 256, 256, DFF, 0,0,0,0,0,0);
    gemm_bf<128,128,4,true,false><<<dim3(DM/128, BLN/128, 1), blk, szT>>>(
        hidb, w2b, nullptr, x2, ffn_sc, 1.f, x1,
        DFF, 1024, 1024, DM, 0,0,0,0,0,0);

    col_mean2<<<dim3(8, BB), 512>>>(x1, xg);
    kernel_pred<<<BB, 256>>>(xg, kp2_w1, kp2_b1, kp2_w2, kp2_b2, tw2, wb, kb);
    decomp_t<<<dim3(8, 4, BB), 256, DSMEM>>>(x1, wb, kb, res, nullptr);
}